// round 4
// baseline (speedup 1.0000x reference)
#include <cuda_runtime.h>
#include <cstdint>

#define B_WIN 4096
#define NTOK  49
#define CDIM  384
#define NH    12
#define HD    32
#define NWIN  64
#define MTOT  (B_WIN*NTOK)          /* 200704 */
#define QKN   (3*CDIM)              /* 1152 */
#define SCALE 0.17677669529663687f  /* 32^-0.5 */

#define BM 128
#define BN 128
#define BK 32
#define AST 36   /* smem row stride in 4B units: conflict-free for qr*8 pattern */

/* permuted-tf32 scratch buffers */
__device__ uint32_t g_xp [(size_t)MTOT*CDIM];          /* x, perm-tf32 */
__device__ uint32_t g_att[(size_t)MTOT*CDIM];          /* attn out, perm-tf32 */
__device__ uint32_t g_wqkv[(size_t)QKN*CDIM];          /* qkv_w perm-tf32 */
__device__ uint32_t g_wproj[(size_t)CDIM*CDIM];        /* proj_w perm-tf32 */
/* q,k: [2][B][H][49][32perm]; v: [B][H][32][64perm-token] */
#define QK_ELEMS ((size_t)2*B_WIN*NH*NTOK*HD)
__device__ uint32_t g_qk[QK_ELEMS];
__device__ uint32_t g_vt[(size_t)B_WIN*NH*HD*64];

__device__ __forceinline__ uint32_t f2tf32(float x){
    uint32_t r; asm("cvt.rna.tf32.f32 %0, %1;\n" : "=r"(r) : "f"(x)); return r;
}
__device__ __forceinline__ void mma8(float c[4], uint32_t a0, uint32_t a1,
                                     uint32_t a2, uint32_t a3,
                                     uint32_t b0, uint32_t b1){
    asm volatile(
      "mma.sync.aligned.m16n8k8.row.col.f32.tf32.tf32.f32 "
      "{%0,%1,%2,%3},{%4,%5,%6,%7},{%8,%9},{%0,%1,%2,%3};\n"
      : "+f"(c[0]), "+f"(c[1]), "+f"(c[2]), "+f"(c[3])
      : "r"(a0), "r"(a1), "r"(a2), "r"(a3), "r"(b0), "r"(b1));
}
__device__ __forceinline__ void cp_async16(void* sdst, const void* gsrc){
    uint32_t s = (uint32_t)__cvta_generic_to_shared(sdst);
    asm volatile("cp.async.cg.shared.global [%0], [%1], 16;\n" :: "r"(s), "l"(gsrc));
}
__device__ __forceinline__ int permk(int k){ return ((k & 3) << 3) + (k >> 2); } /* k<32 */

/* -------- pre-pass: fp32 -> permuted tf32 (perm within each 32-elem block) */
__global__ void __launch_bounds__(256)
perm_cvt_kernel(const float* __restrict__ in, uint32_t* __restrict__ out, int nchunks)
{
    int c = blockIdx.x*256 + threadIdx.x;
    if (c >= nchunks) return;
    int blk = c >> 3, t = c & 7;
    const float4 v = *(const float4*)(in + (size_t)blk*32 + t*4);
    float vv[4] = {v.x, v.y, v.z, v.w};
    #pragma unroll
    for (int j = 0; j < 4; j++){
        int k = t*4 + j;
        out[(size_t)blk*32 + permk(k)] = f2tf32(vv[j]);
    }
}

/* ---------------- GEMM: C = A(MxK) * B(NxK)^T + bias, A/B perm-tf32 --------
   MODE 0: A = g_att, write fp32 out[m*N+n] (proj)
   MODE 1: A = g_xp, scatter q*SCALE,k (perm-d) and v^T (perm-tok) tf32       */
template<int MODE>
__global__ void __launch_bounds__(256, 2)
gemm_tn_kernel(const uint32_t* __restrict__ Bw,
               const float* __restrict__ bias, float* __restrict__ out,
               int N, int K)
{
    extern __shared__ uint32_t smem[];
    uint32_t* As = smem;                 /* [2][BM][AST] */
    uint32_t* Bs = smem + 2*BM*AST;      /* [2][BN][AST] */

    const int bm = blockIdx.y, bn = blockIdx.x;
    const int tid = threadIdx.x;
    const int warp = tid >> 5, lane = tid & 31;
    const int wm = warp >> 2, wn = warp & 3;     /* 2 x 4 warps, warp tile 64x32 */
    const int qt = lane >> 2, qr = lane & 3;

    const uint32_t* Ap = (MODE == 0) ? g_att : g_xp;

    float acc[4][4][4];
    #pragma unroll
    for (int i=0;i<4;i++)
      #pragma unroll
      for (int j=0;j<4;j++)
        #pragma unroll
        for (int c=0;c<4;c++) acc[i][j][c]=0.f;

    const int nK = K / BK;

    #define LOAD_TILE(buf, ksi) do {                                              \
        int koff = (ksi)*BK;                                                      \
        _Pragma("unroll")                                                         \
        for (int i=0;i<4;i++){                                                    \
            int chunk = tid + 256*i;                                              \
            int row = chunk >> 3; int c4 = (chunk & 7) << 2;                      \
            cp_async16(&As[(buf)*BM*AST + row*AST + c4],                          \
                       Ap + (size_t)(bm*BM + row)*K + koff + c4);                 \
            cp_async16(&Bs[(buf)*BN*AST + row*AST + c4],                          \
                       Bw + (size_t)(bn*BN + row)*K + koff + c4);                 \
        }                                                                         \
        asm volatile("cp.async.commit_group;\n" ::);                              \
    } while(0)

    LOAD_TILE(0, 0);

    for (int ks = 0; ks < nK; ks++){
        asm volatile("cp.async.wait_group 0;\n" ::);
        __syncthreads();
        if (ks + 1 < nK) LOAD_TILE((ks+1)&1, ks+1);

        const uint32_t* Ab = &As[(ks&1)*BM*AST + (wm*64)*AST + qr*8];
        const uint32_t* Bb = &Bs[(ks&1)*BN*AST + (wn*32)*AST + qr*8];

        #pragma unroll
        for (int half = 0; half < 2; half++){
            uint32_t Bf[4][4];
            #pragma unroll
            for (int nt=0; nt<4; nt++)
                *(uint4*)Bf[nt] = *(const uint4*)&Bb[(nt*8+qt)*AST + half*4];
            #pragma unroll
            for (int mt=0; mt<4; mt++){
                uint32_t A0[4], A1[4];
                *(uint4*)A0 = *(const uint4*)&Ab[(mt*16+qt  )*AST + half*4];
                *(uint4*)A1 = *(const uint4*)&Ab[(mt*16+qt+8)*AST + half*4];
                #pragma unroll
                for (int kl=0; kl<2; kl++)
                    #pragma unroll
                    for (int nt=0; nt<4; nt++)
                        mma8(acc[mt][nt], A0[2*kl], A1[2*kl], A0[2*kl+1], A1[2*kl+1],
                             Bf[nt][2*kl], Bf[nt][2*kl+1]);
            }
        }
    }
    #undef LOAD_TILE

    /* ---- epilogue ---- */
    if (MODE == 1){
        #pragma unroll
        for (int mt=0; mt<4; mt++){
            #pragma unroll
            for (int cc=0; cc<2; cc++){
                int gm  = bm*BM + wm*64 + mt*16 + qt + cc*8;
                int bwi = gm / NTOK;
                int tok = gm - bwi*NTOK;
                #pragma unroll
                for (int nt=0; nt<4; nt++){
                    #pragma unroll
                    for (int p=0; p<2; p++){
                        int gn = bn*BN + wn*32 + nt*8 + 2*qr + p;
                        float v = acc[mt][nt][cc*2 + p] + bias[gn];
                        int which = gn / CDIM;
                        int rest  = gn - which*CDIM;
                        int h = rest >> 5, d = rest & 31;
                        if (which == 0){
                            v *= SCALE;
                            g_qk[(((size_t)bwi)*NH + h)*(NTOK*HD)
                                 + tok*HD + permk(d)] = f2tf32(v);
                        } else if (which == 1){
                            g_qk[(size_t)B_WIN*NH*NTOK*HD
                                 + (((size_t)bwi)*NH + h)*(NTOK*HD)
                                 + tok*HD + permk(d)] = f2tf32(v);
                        } else {
                            g_vt[(((size_t)bwi)*NH + h)*(HD*64)
                                 + d*64 + (tok & 32) + permk(tok & 31)] = f2tf32(v);
                        }
                    }
                }
            }
        }
    } else {
        #pragma unroll
        for (int mt=0; mt<4; mt++){
            #pragma unroll
            for (int cc=0; cc<2; cc++){
                int gm = bm*BM + wm*64 + mt*16 + qt + cc*8;
                #pragma unroll
                for (int nt=0; nt<4; nt++){
                    #pragma unroll
                    for (int p=0; p<2; p++){
                        int gn = bn*BN + wn*32 + nt*8 + 2*qr + p;
                        out[(size_t)gm*N + gn] = acc[mt][nt][cc*2 + p] + bias[gn];
                    }
                }
            }
        }
    }
}

/* ---------------- attention: one CTA per (b, h) ---------------- */
__global__ void __launch_bounds__(128)
attn_kernel(const float* __restrict__ mask, const float* __restrict__ rpb)
{
    __shared__ uint32_t qs[64*36], ksm[64*36], vsm[32*68], ps[64*68];

    const int b = blockIdx.y, h = blockIdx.x;
    const int tid = threadIdx.x;
    const int warp = tid >> 5, lane = tid & 31;
    const int qt = lane >> 2, qr = lane & 3;

    const size_t base = ((size_t)b*NH + h)*(NTOK*HD);
    const uint32_t* qg = g_qk + base;
    const uint32_t* kg = g_qk + (size_t)B_WIN*NH*NTOK*HD + base;
    const uint32_t* vt = g_vt + ((size_t)b*NH + h)*(HD*64);

    for (int idx = tid; idx < 64*32; idx += 128){
        int r = idx >> 5, c = idx & 31;
        uint32_t q = 0u, k = 0u;
        if (r < NTOK){ q = qg[idx]; k = kg[idx]; }
        qs [r*36 + c] = q;
        ksm[r*36 + c] = k;
    }
    for (int idx = tid; idx < 32*64; idx += 128){
        int r = idx >> 6, c = idx & 63;
        vsm[r*68 + c] = vt[idx];
    }
    __syncthreads();

    const int r0 = warp*16 + qt;

    /* S = q @ k^T  (64x64; this warp: 16-row slab) */
    float S[8][4];
    #pragma unroll
    for (int nt=0; nt<8; nt++)
        #pragma unroll
        for (int c=0; c<4; c++) S[nt][c] = 0.f;

    #pragma unroll
    for (int half=0; half<2; half++){
        uint32_t A0[4], A1[4];
        *(uint4*)A0 = *(const uint4*)&qs[ r0     *36 + qr*8 + half*4];
        *(uint4*)A1 = *(const uint4*)&qs[(r0 + 8)*36 + qr*8 + half*4];
        #pragma unroll
        for (int nt=0; nt<8; nt++){
            uint32_t Bf[4];
            *(uint4*)Bf = *(const uint4*)&ksm[(nt*8+qt)*36 + qr*8 + half*4];
            #pragma unroll
            for (int kl=0; kl<2; kl++)
                mma8(S[nt], A0[2*kl], A1[2*kl], A0[2*kl+1], A1[2*kl+1],
                     Bf[2*kl], Bf[2*kl+1]);
        }
    }

    /* + rpb + mask, pad cols>=49 with -1e30 */
    const float* mrow = mask + (size_t)(b & (NWIN-1))*NTOK*NTOK;
    #pragma unroll
    for (int nt=0; nt<8; nt++){
        #pragma unroll
        for (int c=0; c<4; c++){
            int row = r0 + ((c >> 1) << 3);
            int m   = nt*8 + 2*qr + (c & 1);
            if (m >= NTOK){
                S[nt][c] = -1e30f;
            } else if (row < NTOK){
                int ri = row / 7, ci = row - ri*7;
                int rj = m   / 7, cj = m   - rj*7;
                int idx = ((ri - rj + 6)*13 + (ci - cj + 6))*NH + h;
                S[nt][c] += rpb[idx] + mrow[row*NTOK + m];
            }
        }
    }

    /* softmax over m (per row: spread across 4 lanes qr=0..3) */
    float mx[2] = {-1e30f, -1e30f};
    #pragma unroll
    for (int nt=0; nt<8; nt++)
        #pragma unroll
        for (int c=0; c<4; c++)
            mx[c>>1] = fmaxf(mx[c>>1], S[nt][c]);
    #pragma unroll
    for (int o=1; o<4; o<<=1){
        mx[0] = fmaxf(mx[0], __shfl_xor_sync(0xffffffffu, mx[0], o));
        mx[1] = fmaxf(mx[1], __shfl_xor_sync(0xffffffffu, mx[1], o));
    }
    float sm[2] = {0.f, 0.f};
    #pragma unroll
    for (int nt=0; nt<8; nt++)
        #pragma unroll
        for (int c=0; c<4; c++){
            S[nt][c] = __expf(S[nt][c] - mx[c>>1]);
            sm[c>>1] += S[nt][c];
        }
    #pragma unroll
    for (int o=1; o<4; o<<=1){
        sm[0] += __shfl_xor_sync(0xffffffffu, sm[0], o);
        sm[1] += __shfl_xor_sync(0xffffffffu, sm[1], o);
    }

    /* P -> smem as perm-tf32 (warp-local 16-row slab) */
    #pragma unroll
    for (int nt=0; nt<8; nt++){
        #pragma unroll
        for (int c=0; c<4; c++){
            int row = r0 + ((c >> 1) << 3);
            int m   = nt*8 + 2*qr + (c & 1);
            ps[row*68 + (m & 32) + permk(m & 31)] = f2tf32(S[nt][c]);
        }
    }
    __syncwarp();

    /* O = P @ v^T  (16x32 per warp; k-dim = 64 tokens) */
    float O[4][4];
    #pragma unroll
    for (int nt=0; nt<4; nt++)
        #pragma unroll
        for (int c=0; c<4; c++) O[nt][c] = 0.f;

    #pragma unroll
    for (int blk=0; blk<2; blk++){
        #pragma unroll
        for (int half=0; half<2; half++){
            uint32_t A0[4], A1[4];
            *(uint4*)A0 = *(const uint4*)&ps[ r0     *68 + blk*32 + qr*8 + half*4];
            *(uint4*)A1 = *(const uint4*)&ps[(r0 + 8)*68 + blk*32 + qr*8 + half*4];
            #pragma unroll
            for (int nt=0; nt<4; nt++){
                uint32_t Bf[4];
                *(uint4*)Bf = *(const uint4*)&vsm[(nt*8+qt)*68 + blk*32 + qr*8 + half*4];
                #pragma unroll
                for (int kl=0; kl<2; kl++)
                    mma8(O[nt], A0[2*kl], A1[2*kl], A0[2*kl+1], A1[2*kl+1],
                         Bf[2*kl], Bf[2*kl+1]);
            }
        }
    }

    const float inv0 = 1.f / sm[0], inv1 = 1.f / sm[1];
    #pragma unroll
    for (int nt=0; nt<4; nt++){
        #pragma unroll
        for (int c=0; c<4; c++){
            int row = r0 + ((c >> 1) << 3);
            if (row < NTOK){
                int d = nt*8 + 2*qr + (c & 1);
                g_att[((size_t)b*NTOK + row)*CDIM + h*HD + permk(d)] =
                    f2tf32(O[nt][c] * ((c >> 1) ? inv1 : inv0));
            }
        }
    }
}

extern "C" void kernel_launch(void* const* d_in, const int* in_sizes, int n_in,
                              void* d_out, int out_size)
{
    const float* x      = (const float*)d_in[0];
    const float* mask   = (const float*)d_in[1];
    const float* qkv_w  = (const float*)d_in[2];
    const float* qkv_b  = (const float*)d_in[3];
    const float* proj_w = (const float*)d_in[4];
    const float* proj_b = (const float*)d_in[5];
    const float* rpb    = (const float*)d_in[6];
    float* out = (float*)d_out;

    uint32_t *xp, *wqkv, *wproj;
    cudaGetSymbolAddress((void**)&xp,    g_xp);
    cudaGetSymbolAddress((void**)&wqkv,  g_wqkv);
    cudaGetSymbolAddress((void**)&wproj, g_wproj);

    /* pre-pass: fp32 -> permuted tf32 */
    {
        int n1 = MTOT*CDIM/4;
        perm_cvt_kernel<<<(n1+255)/256, 256>>>(x, xp, n1);
        int n2 = QKN*CDIM/4;
        perm_cvt_kernel<<<(n2+255)/256, 256>>>(qkv_w, wqkv, n2);
        int n3 = CDIM*CDIM/4;
        perm_cvt_kernel<<<(n3+255)/256, 256>>>(proj_w, wproj, n3);
    }

    const size_t smem_bytes = (size_t)2*(BM + BN)*AST*sizeof(uint32_t); /* 73728 */
    cudaFuncSetAttribute(gemm_tn_kernel<0>,
                         cudaFuncAttributeMaxDynamicSharedMemorySize, (int)smem_bytes);
    cudaFuncSetAttribute(gemm_tn_kernel<1>,
                         cudaFuncAttributeMaxDynamicSharedMemorySize, (int)smem_bytes);

    /* K1: qkv = x @ qkv_w^T + b  -> q,k (perm-d) and v^T (perm-tok), tf32 */
    gemm_tn_kernel<1><<<dim3(QKN/BN, MTOT/BM), 256, smem_bytes>>>(
        wqkv, qkv_b, nullptr, QKN, CDIM);

    /* K2: per-(window, head) attention */
    attn_kernel<<<dim3(NH, B_WIN), 128>>>(mask, rpb);

    /* K3: out = attn_out @ proj_w^T + b */
    gemm_tn_kernel<0><<<dim3(CDIM/BN, MTOT/BM), 256, smem_bytes>>>(
        wproj, proj_b, out, CDIM, CDIM);
}

// round 5
// speedup vs baseline: 2.0650x; 2.0650x over previous
#include <cuda_runtime.h>
#include <cuda_fp16.h>
#include <cstdint>

#define B_WIN 4096
#define NTOK  49
#define CDIM  384
#define NH    12
#define HD    32
#define NWIN  64
#define MTOT  (B_WIN*NTOK)          /* 200704 */
#define QKN   (3*CDIM)              /* 1152 */
#define SCALE 0.17677669529663687f  /* 32^-0.5 */

#define BM 128
#define BN 128
#define BK 32
#define SAW 20   /* smem row stride in 32-bit words (= 40 halves = 80B): conflict-free */

/* fp16 scratch */
__device__ __half g_xh  [(size_t)MTOT*CDIM];
__device__ __half g_atth[(size_t)MTOT*CDIM];
__device__ __half g_wqkv[(size_t)QKN*CDIM];
__device__ __half g_wproj[(size_t)CDIM*CDIM];
/* q,k: [2][B][H][49][32] half; v^T: [B][H][32 d][64 tok] half (tok 49..63 stay 0) */
__device__ __half g_qk[(size_t)2*B_WIN*NH*NTOK*HD];
__device__ __half g_vt[(size_t)B_WIN*NH*HD*64];

__device__ __forceinline__ void mma16(float c[4], uint32_t a0, uint32_t a1,
                                      uint32_t a2, uint32_t a3,
                                      uint32_t b0, uint32_t b1){
    asm volatile(
      "mma.sync.aligned.m16n8k16.row.col.f32.f16.f16.f32 "
      "{%0,%1,%2,%3},{%4,%5,%6,%7},{%8,%9},{%0,%1,%2,%3};\n"
      : "+f"(c[0]), "+f"(c[1]), "+f"(c[2]), "+f"(c[3])
      : "r"(a0), "r"(a1), "r"(a2), "r"(a3), "r"(b0), "r"(b1));
}
__device__ __forceinline__ void cp_async16(void* sdst, const void* gsrc){
    uint32_t s = (uint32_t)__cvta_generic_to_shared(sdst);
    asm volatile("cp.async.cg.shared.global [%0], [%1], 16;\n" :: "r"(s), "l"(gsrc));
}
__device__ __forceinline__ uint32_t h2u(__half2 h){ return *(uint32_t*)&h; }

/* -------- pre-pass: fp32 -> fp16 -------- */
__global__ void __launch_bounds__(256)
cvt_h_kernel(const float* __restrict__ in, __half* __restrict__ out, int n4)
{
    int i = blockIdx.x*256 + threadIdx.x;
    if (i >= n4) return;
    float4 v = ((const float4*)in)[i];
    __half2 lo = __floats2half2_rn(v.x, v.y);
    __half2 hi = __floats2half2_rn(v.z, v.w);
    ((__half2*)out)[2*i  ] = lo;
    ((__half2*)out)[2*i+1] = hi;
}

/* ---------------- GEMM: C = A(MxK) * B(NxK)^T + bias, fp16 in, fp32 acc ----
   MODE 0: A = g_atth, write fp32 out (proj)
   MODE 1: A = g_xh, scatter q*SCALE,k -> g_qk and v^T -> g_vt (fp16)         */
template<int MODE>
__global__ void __launch_bounds__(256, 2)
gemm_tn_kernel(const __half* __restrict__ Bw,
               const float* __restrict__ bias, float* __restrict__ out,
               int N, int K)
{
    extern __shared__ uint32_t smem[];
    uint32_t* As = smem;                 /* [2][BM][SAW] */
    uint32_t* Bs = smem + 2*BM*SAW;      /* [2][BN][SAW] */

    const int bm = blockIdx.y, bn = blockIdx.x;
    const int tid = threadIdx.x;
    const int warp = tid >> 5, lane = tid & 31;
    const int wm = warp >> 2, wn = warp & 3;     /* 2x4 warps; warp tile 64x32 */
    const int qt = lane >> 2, qr = lane & 3;

    const __half* Ap = (MODE == 0) ? g_atth : g_xh;

    float acc[4][4][4];
    #pragma unroll
    for (int i=0;i<4;i++)
      #pragma unroll
      for (int j=0;j<4;j++)
        #pragma unroll
        for (int c=0;c<4;c++) acc[i][j][c]=0.f;

    const int nK = K / BK;

    /* each tile: A 128 rows x 32 halves (4x16B chunks), B same -> 1024 chunks */
    #define LOAD_TILE(buf, ksi) do {                                              \
        int koff = (ksi)*BK;                                                      \
        _Pragma("unroll")                                                         \
        for (int i=0;i<4;i++){                                                    \
            int chunk = tid + 256*i;                                              \
            int mat = chunk >> 9; int ch = chunk & 511;                           \
            int row = ch >> 2, c16 = ch & 3;                                      \
            const __half* g = mat                                                 \
              ? Bw + (size_t)(bn*BN + row)*K + koff + c16*8                       \
              : Ap + (size_t)(bm*BM + row)*K + koff + c16*8;                      \
            uint32_t* s = (mat ? &Bs[(buf)*BN*SAW] : &As[(buf)*BM*SAW])           \
                          + row*SAW + c16*4;                                      \
            cp_async16(s, g);                                                     \
        }                                                                         \
        asm volatile("cp.async.commit_group;\n" ::);                              \
    } while(0)

    LOAD_TILE(0, 0);

    for (int ks = 0; ks < nK; ks++){
        asm volatile("cp.async.wait_group 0;\n" ::);
        __syncthreads();
        if (ks + 1 < nK) LOAD_TILE((ks+1)&1, ks+1);

        const uint32_t* Ab = &As[(ks&1)*BM*SAW + (wm*64)*SAW + qr];
        const uint32_t* Bb = &Bs[(ks&1)*BN*SAW + (wn*32)*SAW + qr];

        #pragma unroll
        for (int kst = 0; kst < 2; kst++){
            uint32_t bf[4][2];
            #pragma unroll
            for (int nt=0; nt<4; nt++){
                bf[nt][0] = Bb[(nt*8+qt)*SAW + kst*8    ];
                bf[nt][1] = Bb[(nt*8+qt)*SAW + kst*8 + 4];
            }
            #pragma unroll
            for (int mt=0; mt<4; mt++){
                uint32_t a0 = Ab[(mt*16+qt  )*SAW + kst*8    ];
                uint32_t a1 = Ab[(mt*16+qt+8)*SAW + kst*8    ];
                uint32_t a2 = Ab[(mt*16+qt  )*SAW + kst*8 + 4];
                uint32_t a3 = Ab[(mt*16+qt+8)*SAW + kst*8 + 4];
                #pragma unroll
                for (int nt=0; nt<4; nt++)
                    mma16(acc[mt][nt], a0, a1, a2, a3, bf[nt][0], bf[nt][1]);
            }
        }
    }
    #undef LOAD_TILE

    /* ---- epilogue ---- */
    if (MODE == 1){
        #pragma unroll
        for (int mt=0; mt<4; mt++){
            #pragma unroll
            for (int cc=0; cc<2; cc++){
                int gm  = bm*BM + wm*64 + mt*16 + qt + cc*8;
                int bwi = gm / NTOK;
                int tok = gm - bwi*NTOK;
                #pragma unroll
                for (int nt=0; nt<4; nt++){
                    int gn0 = bn*BN + wn*32 + nt*8 + 2*qr;
                    float v0 = acc[mt][nt][cc*2    ] + bias[gn0];
                    float v1 = acc[mt][nt][cc*2 + 1] + bias[gn0+1];
                    int which = gn0 / CDIM;
                    int rest  = gn0 - which*CDIM;
                    int h = rest >> 5, d = rest & 31;
                    if (which == 0){
                        v0 *= SCALE; v1 *= SCALE;
                        *(__half2*)&g_qk[(((size_t)bwi)*NH + h)*(NTOK*HD)
                                         + tok*HD + d] = __floats2half2_rn(v0, v1);
                    } else if (which == 1){
                        *(__half2*)&g_qk[(size_t)B_WIN*NH*NTOK*HD
                                         + (((size_t)bwi)*NH + h)*(NTOK*HD)
                                         + tok*HD + d] = __floats2half2_rn(v0, v1);
                    } else {
                        __half* vb = &g_vt[(((size_t)bwi)*NH + h)*(HD*64)];
                        vb[(size_t)d*64 + tok]     = __float2half_rn(v0);
                        vb[(size_t)(d+1)*64 + tok] = __float2half_rn(v1);
                    }
                }
            }
        }
    } else {
        #pragma unroll
        for (int mt=0; mt<4; mt++){
            #pragma unroll
            for (int cc=0; cc<2; cc++){
                int gm = bm*BM + wm*64 + mt*16 + qt + cc*8;
                #pragma unroll
                for (int nt=0; nt<4; nt++){
                    int gn0 = bn*BN + wn*32 + nt*8 + 2*qr;
                    out[(size_t)gm*N + gn0    ] = acc[mt][nt][cc*2    ] + bias[gn0];
                    out[(size_t)gm*N + gn0 + 1] = acc[mt][nt][cc*2 + 1] + bias[gn0+1];
                }
            }
        }
    }
}

/* ---------------- attention: one CTA per (b, h), fp16 mma ---------------- */
__global__ void __launch_bounds__(128)
attn_kernel(const float* __restrict__ mask, const float* __restrict__ rpb)
{
    /* strides in words: qs/ksm 20 (40 halves), vsm/ps 36 (72 halves) */
    __shared__ uint32_t qs[64*20], ksm[64*20], vsm[32*36], ps[64*36];

    const int b = blockIdx.y, h = blockIdx.x;
    const int tid = threadIdx.x;
    const int warp = tid >> 5, lane = tid & 31;
    const int qt = lane >> 2, qr = lane & 3;

    const size_t base = ((size_t)b*NH + h)*(NTOK*HD);
    const uint32_t* qg = (const uint32_t*)(g_qk + base);
    const uint32_t* kg = (const uint32_t*)(g_qk + (size_t)B_WIN*NH*NTOK*HD + base);
    const uint32_t* vg = (const uint32_t*)(g_vt + ((size_t)b*NH + h)*(HD*64));

    for (int idx = tid; idx < 64*16; idx += 128){
        int r = idx >> 4, c = idx & 15;
        uint32_t q = 0u, k = 0u;
        if (r < NTOK){ q = qg[r*16 + c]; k = kg[r*16 + c]; }
        qs [r*20 + c] = q;
        ksm[r*20 + c] = k;
    }
    for (int idx = tid; idx < 32*32; idx += 128){
        int r = idx >> 5, c = idx & 31;
        vsm[r*36 + c] = vg[idx];
    }
    __syncthreads();

    const int r0 = warp*16 + qt;

    /* S = q @ k^T  (this warp: rows r0, r0+8 of a 16-row slab; 64 cols) */
    float S[8][4];
    #pragma unroll
    for (int nt=0; nt<8; nt++)
        #pragma unroll
        for (int c=0; c<4; c++) S[nt][c] = 0.f;

    #pragma unroll
    for (int kst=0; kst<2; kst++){
        uint32_t a0 = qs[ r0     *20 + kst*8 + qr    ];
        uint32_t a1 = qs[(r0 + 8)*20 + kst*8 + qr    ];
        uint32_t a2 = qs[ r0     *20 + kst*8 + qr + 4];
        uint32_t a3 = qs[(r0 + 8)*20 + kst*8 + qr + 4];
        #pragma unroll
        for (int nt=0; nt<8; nt++){
            uint32_t b0 = ksm[(nt*8+qt)*20 + kst*8 + qr    ];
            uint32_t b1 = ksm[(nt*8+qt)*20 + kst*8 + qr + 4];
            mma16(S[nt], a0, a1, a2, a3, b0, b1);
        }
    }

    /* + rpb + mask, pad cols>=49 with -1e30 */
    const float* mrow = mask + (size_t)(b & (NWIN-1))*NTOK*NTOK;
    #pragma unroll
    for (int nt=0; nt<8; nt++){
        #pragma unroll
        for (int c=0; c<4; c++){
            int row = r0 + ((c >> 1) << 3);
            int m   = nt*8 + 2*qr + (c & 1);
            if (m >= NTOK){
                S[nt][c] = -1e30f;
            } else if (row < NTOK){
                int ri = row / 7, ci = row - ri*7;
                int rj = m   / 7, cj = m   - rj*7;
                int idx = ((ri - rj + 6)*13 + (ci - cj + 6))*NH + h;
                S[nt][c] += rpb[idx] + mrow[row*NTOK + m];
            }
        }
    }

    /* softmax over m (per row, spread across 4 lanes qr) */
    float mx[2] = {-1e30f, -1e30f};
    #pragma unroll
    for (int nt=0; nt<8; nt++)
        #pragma unroll
        for (int c=0; c<4; c++)
            mx[c>>1] = fmaxf(mx[c>>1], S[nt][c]);
    #pragma unroll
    for (int o=1; o<4; o<<=1){
        mx[0] = fmaxf(mx[0], __shfl_xor_sync(0xffffffffu, mx[0], o));
        mx[1] = fmaxf(mx[1], __shfl_xor_sync(0xffffffffu, mx[1], o));
    }
    float sm[2] = {0.f, 0.f};
    #pragma unroll
    for (int nt=0; nt<8; nt++)
        #pragma unroll
        for (int c=0; c<4; c++){
            S[nt][c] = __expf(S[nt][c] - mx[c>>1]);
            sm[c>>1] += S[nt][c];
        }
    #pragma unroll
    for (int o=1; o<4; o<<=1){
        sm[0] += __shfl_xor_sync(0xffffffffu, sm[0], o);
        sm[1] += __shfl_xor_sync(0xffffffffu, sm[1], o);
    }

    /* P -> smem fp16 (warp-local 16-row slab), m pairs packed in half2 */
    #pragma unroll
    for (int nt=0; nt<8; nt++){
        #pragma unroll
        for (int hr=0; hr<2; hr++){
            int row = r0 + hr*8;
            ps[row*36 + nt*4 + qr] =
                h2u(__floats2half2_rn(S[nt][hr*2], S[nt][hr*2+1]));
        }
    }
    __syncwarp();

    /* O = P @ v  (16x32 per warp; k-dim = 64 tokens) */
    float O[4][4];
    #pragma unroll
    for (int nt=0; nt<4; nt++)
        #pragma unroll
        for (int c=0; c<4; c++) O[nt][c] = 0.f;

    #pragma unroll
    for (int ksx=0; ksx<4; ksx++){
        uint32_t a0 = ps[ r0     *36 + ksx*8 + qr    ];
        uint32_t a1 = ps[(r0 + 8)*36 + ksx*8 + qr    ];
        uint32_t a2 = ps[ r0     *36 + ksx*8 + qr + 4];
        uint32_t a3 = ps[(r0 + 8)*36 + ksx*8 + qr + 4];
        #pragma unroll
        for (int nt=0; nt<4; nt++){
            uint32_t b0 = vsm[(nt*8+qt)*36 + ksx*8 + qr    ];
            uint32_t b1 = vsm[(nt*8+qt)*36 + ksx*8 + qr + 4];
            mma16(O[nt], a0, a1, a2, a3, b0, b1);
        }
    }

    const float inv0 = 1.f / sm[0], inv1 = 1.f / sm[1];
    #pragma unroll
    for (int nt=0; nt<4; nt++){
        #pragma unroll
        for (int hr=0; hr<2; hr++){
            int row = r0 + hr*8;
            if (row < NTOK){
                int d = nt*8 + 2*qr;
                float inv = hr ? inv1 : inv0;
                *(__half2*)&g_atth[((size_t)b*NTOK + row)*CDIM + h*HD + d] =
                    __floats2half2_rn(O[nt][hr*2]*inv, O[nt][hr*2+1]*inv);
            }
        }
    }
}

extern "C" void kernel_launch(void* const* d_in, const int* in_sizes, int n_in,
                              void* d_out, int out_size)
{
    const float* x      = (const float*)d_in[0];
    const float* mask   = (const float*)d_in[1];
    const float* qkv_w  = (const float*)d_in[2];
    const float* qkv_b  = (const float*)d_in[3];
    const float* proj_w = (const float*)d_in[4];
    const float* proj_b = (const float*)d_in[5];
    const float* rpb    = (const float*)d_in[6];
    float* out = (float*)d_out;

    __half *xh, *wqkv, *wproj;
    cudaGetSymbolAddress((void**)&xh,    g_xh);
    cudaGetSymbolAddress((void**)&wqkv,  g_wqkv);
    cudaGetSymbolAddress((void**)&wproj, g_wproj);

    /* pre-pass: fp32 -> fp16 */
    {
        int n1 = MTOT*CDIM/4;
        cvt_h_kernel<<<(n1+255)/256, 256>>>(x, xh, n1);
        int n2 = QKN*CDIM/4;
        cvt_h_kernel<<<(n2+255)/256, 256>>>(qkv_w, wqkv, n2);
        int n3 = CDIM*CDIM/4;
        cvt_h_kernel<<<(n3+255)/256, 256>>>(proj_w, wproj, n3);
    }

    const size_t smem_bytes = (size_t)4*(BM + BN)*SAW*sizeof(uint32_t)/2; /* 40960 */

    /* K1: qkv = x @ qkv_w^T + b -> q*SCALE,k -> g_qk ; v^T -> g_vt */
    gemm_tn_kernel<1><<<dim3(QKN/BN, MTOT/BM), 256, smem_bytes>>>(
        wqkv, qkv_b, nullptr, QKN, CDIM);

    /* K2: per-(window, head) attention */
    attn_kernel<<<dim3(NH, B_WIN), 128>>>(mask, rpb);

    /* K3: out = attn_out @ proj_w^T + b */
    gemm_tn_kernel<0><<<dim3(CDIM/BN, MTOT/BM), 256, smem_bytes>>>(
        wproj, proj_b, out, CDIM, CDIM);
}

// round 7
// speedup vs baseline: 2.6151x; 1.2664x over previous
#include <cuda_runtime.h>
#include <cuda_fp16.h>
#include <cstdint>

#define B_WIN 4096
#define NTOK  49
#define CDIM  384
#define NH    12
#define HD    32
#define NWIN  64
#define MTOT  (B_WIN*NTOK)          /* 200704 */
#define QKN   (3*CDIM)              /* 1152 */
#define SCALE 0.17677669529663687f  /* 32^-0.5 */

#define BM 128
#define BN 128
#define BK 64
#define SAW 36   /* smem row stride in 32-bit words (64 halves data + pad) */

/* fp16 scratch */
__device__ __half g_xh  [(size_t)MTOT*CDIM];
__device__ __half g_atth[(size_t)MTOT*CDIM];
__device__ __half g_wqkv[(size_t)QKN*CDIM];
__device__ __half g_wproj[(size_t)CDIM*CDIM];
/* q,k: [2][B][H][49][32] half; v^T: [B][H][32 d][64 tok] half */
__device__ __half g_qk[(size_t)2*B_WIN*NH*NTOK*HD];
__device__ __half g_vt[(size_t)B_WIN*NH*HD*64];
/* combined rpb+mask: [64 w][12 h][49*49] fp32, ~7.4MB (L2-resident) */
__device__ float g_cmb[(size_t)NWIN*NH*NTOK*NTOK];

__device__ __forceinline__ void mma16(float c[4], uint32_t a0, uint32_t a1,
                                      uint32_t a2, uint32_t a3,
                                      uint32_t b0, uint32_t b1){
    asm volatile(
      "mma.sync.aligned.m16n8k16.row.col.f32.f16.f16.f32 "
      "{%0,%1,%2,%3},{%4,%5,%6,%7},{%8,%9},{%0,%1,%2,%3};\n"
      : "+f"(c[0]), "+f"(c[1]), "+f"(c[2]), "+f"(c[3])
      : "r"(a0), "r"(a1), "r"(a2), "r"(a3), "r"(b0), "r"(b1));
}
__device__ __forceinline__ void ldsm_x4(uint32_t r[4], uint32_t saddr){
    asm volatile("ldmatrix.sync.aligned.m8n8.x4.shared.b16 {%0,%1,%2,%3}, [%4];\n"
      : "=r"(r[0]), "=r"(r[1]), "=r"(r[2]), "=r"(r[3]) : "r"(saddr));
}
__device__ __forceinline__ void cp_async16(void* sdst, const void* gsrc){
    uint32_t s = (uint32_t)__cvta_generic_to_shared(sdst);
    asm volatile("cp.async.cg.shared.global [%0], [%1], 16;\n" :: "r"(s), "l"(gsrc));
}
__device__ __forceinline__ uint32_t h2u(__half2 h){ return *(uint32_t*)&h; }

/* -------- pre-pass: fp32 -> fp16 -------- */
__global__ void __launch_bounds__(256)
cvt_h_kernel(const float* __restrict__ in, __half* __restrict__ out, int n4)
{
    int i = blockIdx.x*256 + threadIdx.x;
    if (i >= n4) return;
    float4 v = ((const float4*)in)[i];
    ((__half2*)out)[2*i  ] = __floats2half2_rn(v.x, v.y);
    ((__half2*)out)[2*i+1] = __floats2half2_rn(v.z, v.w);
}

/* -------- pre-pass: cmb[w][h][row][m] = rpb[relidx(row,m)][h] + mask[w][row][m] */
__global__ void __launch_bounds__(256)
cmb_kernel(const float* __restrict__ mask, const float* __restrict__ rpb)
{
    int i = blockIdx.x*256 + threadIdx.x;
    if (i >= NWIN*NH*NTOK*NTOK) return;
    int w  = i / (NH*NTOK*NTOK);
    int r1 = i - w*(NH*NTOK*NTOK);
    int h  = r1 / (NTOK*NTOK);
    int rm = r1 - h*(NTOK*NTOK);
    int row = rm / NTOK, m = rm - (rm/NTOK)*NTOK;
    int ri = row/7, ci = row - ri*7;
    int rj = m  /7, cj = m   - rj*7;
    int idx = ((ri - rj + 6)*13 + (ci - cj + 6))*NH + h;
    g_cmb[i] = rpb[idx] + mask[(size_t)w*NTOK*NTOK + rm];
}

/* ---------------- GEMM: C = A(MxK) * B(NxK)^T + bias, fp16 in, fp32 acc ----
   MODE 0: A = g_atth, write fp32 out (proj)
   MODE 1: A = g_xh, scatter q*SCALE,k -> g_qk and v^T -> g_vt (fp16)         */
template<int MODE>
__global__ void __launch_bounds__(256, 2)
gemm_tn_kernel(const __half* __restrict__ Bw,
               const float* __restrict__ bias, float* __restrict__ out,
               int N, int K)
{
    extern __shared__ uint32_t smem[];
    /* layout (words): As[2][BM][SAW], then Bs[2][BN][SAW] */
    uint32_t* As = smem;
    uint32_t* Bs = smem + 2*BM*SAW;

    const int bm = blockIdx.y, bn = blockIdx.x;
    const int tid = threadIdx.x;
    const int warp = tid >> 5, lane = tid & 31;
    const int wm = warp >> 2, wn = warp & 3;     /* 2x4 warps; warp tile 64x32 */
    const int qt = lane >> 2, qr = lane & 3;

    const __half* Ap = (MODE == 0) ? g_atth : g_xh;

    float acc[4][4][4];
    #pragma unroll
    for (int i=0;i<4;i++)
      #pragma unroll
      for (int j=0;j<4;j++)
        #pragma unroll
        for (int c=0;c<4;c++) acc[i][j][c]=0.f;

    const int nK = K / BK;   /* 6 */

    /* ldmatrix per-lane base addresses (bytes, shared state space) */
    const uint32_t s0 = (uint32_t)__cvta_generic_to_shared(smem);
    const uint32_t aAddr0 = s0
        + ((wm*64 + (lane & 15))*SAW + (lane >> 4)*4)*4;
    const uint32_t bAddr0 = s0 + 2*BM*SAW*4
        + ((wn*32 + (lane & 7) + ((lane >> 4) & 1)*8)*SAW + ((lane >> 3) & 1)*4)*4;
    const uint32_t ASTG = BM*SAW*4;   /* 18432 B per A stage */
    const uint32_t BSTG = BN*SAW*4;

    /* tile: A 128x64h (8x16B chunks/row) + B same -> 2048 chunks, 8/thread */
    #define LOAD_TILE(buf, ksi) do {                                              \
        int koff = (ksi)*BK;                                                      \
        _Pragma("unroll")                                                         \
        for (int i=0;i<8;i++){                                                    \
            int chunk = tid + 256*i;                                              \
            int mat = chunk >> 10; int ch = chunk & 1023;                         \
            int row = ch >> 3, c16 = ch & 7;                                      \
            const __half* g = mat                                                 \
              ? Bw + (size_t)(bn*BN + row)*K + koff + c16*8                       \
              : Ap + (size_t)(bm*BM + row)*K + koff + c16*8;                      \
            uint32_t* s = (mat ? &Bs[(buf)*BN*SAW] : &As[(buf)*BM*SAW])           \
                          + row*SAW + c16*4;                                      \
            cp_async16(s, g);                                                     \
        }                                                                         \
        asm volatile("cp.async.commit_group;\n" ::);                              \
    } while(0)

    LOAD_TILE(0, 0);

    for (int ks = 0; ks < nK; ks++){
        asm volatile("cp.async.wait_group 0;\n" ::);
        __syncthreads();
        if (ks + 1 < nK) LOAD_TILE((ks+1)&1, ks+1);

        const uint32_t aB = aAddr0 + (ks&1)*ASTG;
        const uint32_t bB = bAddr0 + (ks&1)*BSTG;

        #pragma unroll
        for (int kst = 0; kst < 4; kst++){
            uint32_t bf[2][4];
            ldsm_x4(bf[0], bB + kst*32);
            ldsm_x4(bf[1], bB + 16*SAW*4 + kst*32);
            uint32_t af[4][4];
            #pragma unroll
            for (int mt=0; mt<4; mt++)
                ldsm_x4(af[mt], aB + mt*16*SAW*4 + kst*32);
            #pragma unroll
            for (int mt=0; mt<4; mt++)
                #pragma unroll
                for (int nt=0; nt<4; nt++)
                    mma16(acc[mt][nt], af[mt][0], af[mt][1], af[mt][2], af[mt][3],
                          bf[nt>>1][(nt&1)*2], bf[nt>>1][(nt&1)*2+1]);
        }
    }
    #undef LOAD_TILE

    /* ---- epilogue ---- */
    if (MODE == 1){
        #pragma unroll
        for (int mt=0; mt<4; mt++){
            #pragma unroll
            for (int cc=0; cc<2; cc++){
                int gm  = bm*BM + wm*64 + mt*16 + qt + cc*8;
                int bwi = gm / NTOK;
                int tok = gm - bwi*NTOK;
                #pragma unroll
                for (int nt=0; nt<4; nt++){
                    int gn0 = bn*BN + wn*32 + nt*8 + 2*qr;
                    float v0 = acc[mt][nt][cc*2    ] + bias[gn0];
                    float v1 = acc[mt][nt][cc*2 + 1] + bias[gn0+1];
                    int which = gn0 / CDIM;
                    int rest  = gn0 - which*CDIM;
                    int h = rest >> 5, d = rest & 31;
                    if (which == 0){
                        v0 *= SCALE; v1 *= SCALE;
                        *(__half2*)&g_qk[(((size_t)bwi)*NH + h)*(NTOK*HD)
                                         + tok*HD + d] = __floats2half2_rn(v0, v1);
                    } else if (which == 1){
                        *(__half2*)&g_qk[(size_t)B_WIN*NH*NTOK*HD
                                         + (((size_t)bwi)*NH + h)*(NTOK*HD)
                                         + tok*HD + d] = __floats2half2_rn(v0, v1);
                    } else {
                        __half* vb = &g_vt[(((size_t)bwi)*NH + h)*(HD*64)];
                        vb[(size_t)d*64 + tok]     = __float2half_rn(v0);
                        vb[(size_t)(d+1)*64 + tok] = __float2half_rn(v1);
                    }
                }
            }
        }
    } else {
        #pragma unroll
        for (int mt=0; mt<4; mt++){
            #pragma unroll
            for (int cc=0; cc<2; cc++){
                int gm = bm*BM + wm*64 + mt*16 + qt + cc*8;
                #pragma unroll
                for (int nt=0; nt<4; nt++){
                    int gn0 = bn*BN + wn*32 + nt*8 + 2*qr;
                    out[(size_t)gm*N + gn0    ] = acc[mt][nt][cc*2    ] + bias[gn0];
                    out[(size_t)gm*N + gn0 + 1] = acc[mt][nt][cc*2 + 1] + bias[gn0+1];
                }
            }
        }
    }
}

/* ---------------- attention: one CTA per (b, h), fp16 mma ---------------- */
__global__ void __launch_bounds__(128)
attn_kernel()
{
    /* strides in words: qs/ksm 20 (40 halves), vsm/ps 36 (72 halves) */
    __shared__ uint32_t qs[64*20], ksm[64*20], vsm[32*36], ps[64*36];

    const int b = blockIdx.y, h = blockIdx.x;
    const int tid = threadIdx.x;
    const int warp = tid >> 5, lane = tid & 31;
    const int qt = lane >> 2, qr = lane & 3;

    const size_t base = ((size_t)b*NH + h)*(NTOK*HD);
    const uint32_t* qg = (const uint32_t*)(g_qk + base);
    const uint32_t* kg = (const uint32_t*)(g_qk + (size_t)B_WIN*NH*NTOK*HD + base);
    const uint32_t* vg = (const uint32_t*)(g_vt + ((size_t)b*NH + h)*(HD*64));
    const float* cmb = g_cmb + ((size_t)(b & (NWIN-1))*NH + h)*(NTOK*NTOK);

    for (int idx = tid; idx < 64*16; idx += 128){
        int r = idx >> 4, c = idx & 15;
        uint32_t q = 0u, k = 0u;
        if (r < NTOK){ q = qg[r*16 + c]; k = kg[r*16 + c]; }
        qs [r*20 + c] = q;
        ksm[r*20 + c] = k;
    }
    for (int idx = tid; idx < 32*32; idx += 128){
        int r = idx >> 5, c = idx & 31;
        vsm[r*36 + c] = vg[idx];
    }
    __syncthreads();

    const int r0 = warp*16 + qt;

    /* S = q @ k^T */
    float S[8][4];
    #pragma unroll
    for (int nt=0; nt<8; nt++)
        #pragma unroll
        for (int c=0; c<4; c++) S[nt][c] = 0.f;

    #pragma unroll
    for (int kst=0; kst<2; kst++){
        uint32_t a0 = qs[ r0     *20 + kst*8 + qr    ];
        uint32_t a1 = qs[(r0 + 8)*20 + kst*8 + qr    ];
        uint32_t a2 = qs[ r0     *20 + kst*8 + qr + 4];
        uint32_t a3 = qs[(r0 + 8)*20 + kst*8 + qr + 4];
        #pragma unroll
        for (int nt=0; nt<8; nt++){
            uint32_t b0 = ksm[(nt*8+qt)*20 + kst*8 + qr    ];
            uint32_t b1 = ksm[(nt*8+qt)*20 + kst*8 + qr + 4];
            mma16(S[nt], a0, a1, a2, a3, b0, b1);
        }
    }

    /* + (rpb+mask) combined, pad cols>=49 with -1e30 */
    #pragma unroll
    for (int nt=0; nt<8; nt++){
        #pragma unroll
        for (int c=0; c<4; c++){
            int row = r0 + ((c >> 1) << 3);
            int m   = nt*8 + 2*qr + (c & 1);
            if (m >= NTOK)       S[nt][c] = -1e30f;
            else if (row < NTOK) S[nt][c] += cmb[row*NTOK + m];
        }
    }

    /* softmax over m */
    float mx[2] = {-1e30f, -1e30f};
    #pragma unroll
    for (int nt=0; nt<8; nt++)
        #pragma unroll
        for (int c=0; c<4; c++)
            mx[c>>1] = fmaxf(mx[c>>1], S[nt][c]);
    #pragma unroll
    for (int o=1; o<4; o<<=1){
        mx[0] = fmaxf(mx[0], __shfl_xor_sync(0xffffffffu, mx[0], o));
        mx[1] = fmaxf(mx[1], __shfl_xor_sync(0xffffffffu, mx[1], o));
    }
    float sm[2] = {0.f, 0.f};
    #pragma unroll
    for (int nt=0; nt<8; nt++)
        #pragma unroll
        for (int c=0; c<4; c++){
            S[nt][c] = __expf(S[nt][c] - mx[c>>1]);
            sm[c>>1] += S[nt][c];
        }
    #pragma unroll
    for (int o=1; o<4; o<<=1){
        sm[0] += __shfl_xor_sync(0xffffffffu, sm[0], o);
        sm[1] += __shfl_xor_sync(0xffffffffu, sm[1], o);
    }

    /* P -> smem fp16 (warp-local 16-row slab) */
    #pragma unroll
    for (int nt=0; nt<8; nt++){
        #pragma unroll
        for (int hr=0; hr<2; hr++){
            int row = r0 + hr*8;
            ps[row*36 + nt*4 + qr] =
                h2u(__floats2half2_rn(S[nt][hr*2], S[nt][hr*2+1]));
        }
    }
    __syncwarp();

    /* O = P @ v */
    float O[4][4];
    #pragma unroll
    for (int nt=0; nt<4; nt++)
        #pragma unroll
        for (int c=0; c<4; c++) O[nt][c] = 0.f;

    #pragma unroll
    for (int ksx=0; ksx<4; ksx++){
        uint32_t a0 = ps[ r0     *36 + ksx*8 + qr    ];
        uint32_t a1 = ps[(r0 + 8)*36 + ksx*8 + qr    ];
        uint32_t a2 = ps[ r0     *36 + ksx*8 + qr + 4];
        uint32_t a3 = ps[(r0 + 8)*36 + ksx*8 + qr + 4];
        #pragma unroll
        for (int nt=0; nt<4; nt++){
            uint32_t b0 = vsm[(nt*8+qt)*36 + ksx*8 + qr    ];
            uint32_t b1 = vsm[(nt*8+qt)*36 + ksx*8 + qr + 4];
            mma16(O[nt], a0, a1, a2, a3, b0, b1);
        }
    }

    const float inv0 = 1.f / sm[0], inv1 = 1.f / sm[1];
    #pragma unroll
    for (int nt=0; nt<4; nt++){
        #pragma unroll
        for (int hr=0; hr<2; hr++){
            int row = r0 + hr*8;
            if (row < NTOK){
                int d = nt*8 + 2*qr;
                float inv = hr ? inv1 : inv0;
                *(__half2*)&g_atth[((size_t)b*NTOK + row)*CDIM + h*HD + d] =
                    __floats2half2_rn(O[nt][hr*2]*inv, O[nt][hr*2+1]*inv);
            }
        }
    }
}

extern "C" void kernel_launch(void* const* d_in, const int* in_sizes, int n_in,
                              void* d_out, int out_size)
{
    const float* x      = (const float*)d_in[0];
    const float* mask   = (const float*)d_in[1];
    const float* qkv_w  = (const float*)d_in[2];
    const float* qkv_b  = (const float*)d_in[3];
    const float* proj_w = (const float*)d_in[4];
    const float* proj_b = (const float*)d_in[5];
    const float* rpb    = (const float*)d_in[6];
    float* out = (float*)d_out;

    __half *xh, *wqkv, *wproj;
    cudaGetSymbolAddress((void**)&xh,    g_xh);
    cudaGetSymbolAddress((void**)&wqkv,  g_wqkv);
    cudaGetSymbolAddress((void**)&wproj, g_wproj);

    /* pre-pass: fp32 -> fp16, and combined rpb+mask table */
    {
        int n1 = MTOT*CDIM/4;
        cvt_h_kernel<<<(n1+255)/256, 256>>>(x, xh, n1);
        int n2 = QKN*CDIM/4;
        cvt_h_kernel<<<(n2+255)/256, 256>>>(qkv_w, wqkv, n2);
        int n3 = CDIM*CDIM/4;
        cvt_h_kernel<<<(n3+255)/256, 256>>>(proj_w, wproj, n3);
        int nc = NWIN*NH*NTOK*NTOK;
        cmb_kernel<<<(nc+255)/256, 256>>>(mask, rpb);
    }

    const size_t smem_bytes = (size_t)2*(BM + BN)*SAW*sizeof(uint32_t); /* 73728 */
    cudaFuncSetAttribute(gemm_tn_kernel<0>,
                         cudaFuncAttributeMaxDynamicSharedMemorySize, (int)smem_bytes);
    cudaFuncSetAttribute(gemm_tn_kernel<1>,
                         cudaFuncAttributeMaxDynamicSharedMemorySize, (int)smem_bytes);

    /* K1: qkv = x @ qkv_w^T + b -> q*SCALE,k -> g_qk ; v^T -> g_vt */
    gemm_tn_kernel<1><<<dim3(QKN/BN, MTOT/BM), 256, smem_bytes>>>(
        wqkv, qkv_b, nullptr, QKN, CDIM);

    /* K2: per-(window, head) attention */
    attn_kernel<<<dim3(NH, B_WIN), 128>>>();

    /* K3: out = attn_out @ proj_w^T + b */
    gemm_tn_kernel<0><<<dim3(CDIM/BN, MTOT/BM), 256, smem_bytes>>>(
        wproj, proj_b, out, CDIM, CDIM);
}

// round 8
// speedup vs baseline: 2.9435x; 1.1256x over previous
#include <cuda_runtime.h>
#include <cuda_fp16.h>
#include <cstdint>

#define B_WIN 4096
#define NTOK  49
#define CDIM  384
#define NH    12
#define HD    32
#define NWIN  64
#define MTOT  (B_WIN*NTOK)          /* 200704 */
#define QKN   (3*CDIM)              /* 1152 */
#define SCALE 0.17677669529663687f  /* 32^-0.5 */

#define BM 128
#define BN 128
#define BK 64
#define SAW 36   /* gemm smem row stride in 32-bit words */

/* fp16 scratch */
__device__ __half g_xh  [(size_t)MTOT*CDIM];
__device__ __half g_atth[(size_t)MTOT*CDIM];
__device__ __half g_wqkv[(size_t)QKN*CDIM];
__device__ __half g_wproj[(size_t)CDIM*CDIM];
/* q,k: [2][B][H][49][32] half; v^T: [B][H][32 d][64 tok] half */
__device__ __half g_qk[(size_t)2*B_WIN*NH*NTOK*HD];
__device__ __half g_vt[(size_t)B_WIN*NH*HD*64];
/* combined rpb+mask, PADDED to 64x64 fp16: [64 w][12 h][64 row][64 m] (~6.3MB) */
__device__ __half g_cmbh[(size_t)NWIN*NH*64*64];

__device__ __forceinline__ void mma16(float c[4], uint32_t a0, uint32_t a1,
                                      uint32_t a2, uint32_t a3,
                                      uint32_t b0, uint32_t b1){
    asm volatile(
      "mma.sync.aligned.m16n8k16.row.col.f32.f16.f16.f32 "
      "{%0,%1,%2,%3},{%4,%5,%6,%7},{%8,%9},{%0,%1,%2,%3};\n"
      : "+f"(c[0]), "+f"(c[1]), "+f"(c[2]), "+f"(c[3])
      : "r"(a0), "r"(a1), "r"(a2), "r"(a3), "r"(b0), "r"(b1));
}
__device__ __forceinline__ void ldsm_x4(uint32_t r[4], uint32_t saddr){
    asm volatile("ldmatrix.sync.aligned.m8n8.x4.shared.b16 {%0,%1,%2,%3}, [%4];\n"
      : "=r"(r[0]), "=r"(r[1]), "=r"(r[2]), "=r"(r[3]) : "r"(saddr));
}
__device__ __forceinline__ void cp_async16(void* sdst, const void* gsrc){
    uint32_t s = (uint32_t)__cvta_generic_to_shared(sdst);
    asm volatile("cp.async.cg.shared.global [%0], [%1], 16;\n" :: "r"(s), "l"(gsrc));
}
__device__ __forceinline__ uint32_t h2u(__half2 h){ return *(uint32_t*)&h; }

/* -------- pre-pass: fp32 -> fp16 -------- */
__global__ void __launch_bounds__(256)
cvt_h_kernel(const float* __restrict__ in, __half* __restrict__ out, int n4)
{
    int i = blockIdx.x*256 + threadIdx.x;
    if (i >= n4) return;
    float4 v = ((const float4*)in)[i];
    ((__half2*)out)[2*i  ] = __floats2half2_rn(v.x, v.y);
    ((__half2*)out)[2*i+1] = __floats2half2_rn(v.z, v.w);
}

/* -------- pre-pass: padded fp16 cmb[w][h][row 64][m 64] -------- */
__global__ void __launch_bounds__(256)
cmb_kernel(const float* __restrict__ mask, const float* __restrict__ rpb)
{
    int i = blockIdx.x*256 + threadIdx.x;
    if (i >= NWIN*NH*64*64) return;
    int w  = i / (NH*64*64);
    int r1 = i - w*(NH*64*64);
    int h  = r1 / (64*64);
    int rm = r1 - h*(64*64);
    int row = rm >> 6, m = rm & 63;
    float val;
    if (m >= NTOK)        val = -30000.f;          /* kills softmax for pad cols */
    else if (row >= NTOK) val = 0.f;               /* unused rows */
    else {
        int ri = row/7, ci = row - ri*7;
        int rj = m  /7, cj = m   - rj*7;
        int idx = ((ri - rj + 6)*13 + (ci - cj + 6))*NH + h;
        val = rpb[idx] + mask[(size_t)w*NTOK*NTOK + row*NTOK + m];
    }
    g_cmbh[i] = __float2half_rn(val);
}

/* ---------------- GEMM: C = A(MxK) * B(NxK)^T + bias, fp16 in, fp32 acc ----
   MODE 0: A = g_atth, write fp32 out (proj)
   MODE 1: A = g_xh, scatter q*SCALE,k -> g_qk and v^T -> g_vt (fp16)         */
template<int MODE>
__global__ void __launch_bounds__(256, 2)
gemm_tn_kernel(const __half* __restrict__ Bw,
               const float* __restrict__ bias, float* __restrict__ out,
               int N, int K)
{
    extern __shared__ uint32_t smem[];
    uint32_t* As = smem;
    uint32_t* Bs = smem + 2*BM*SAW;

    const int bm = blockIdx.y, bn = blockIdx.x;
    const int tid = threadIdx.x;
    const int warp = tid >> 5, lane = tid & 31;
    const int wm = warp >> 2, wn = warp & 3;
    const int qt = lane >> 2, qr = lane & 3;

    const __half* Ap = (MODE == 0) ? g_atth : g_xh;

    float acc[4][4][4];
    #pragma unroll
    for (int i=0;i<4;i++)
      #pragma unroll
      for (int j=0;j<4;j++)
        #pragma unroll
        for (int c=0;c<4;c++) acc[i][j][c]=0.f;

    const int nK = K / BK;

    const uint32_t s0 = (uint32_t)__cvta_generic_to_shared(smem);
    const uint32_t aAddr0 = s0
        + ((wm*64 + (lane & 15))*SAW + (lane >> 4)*4)*4;
    const uint32_t bAddr0 = s0 + 2*BM*SAW*4
        + ((wn*32 + (lane & 7) + ((lane >> 4) & 1)*8)*SAW + ((lane >> 3) & 1)*4)*4;
    const uint32_t ASTG = BM*SAW*4;
    const uint32_t BSTG = BN*SAW*4;

    #define LOAD_TILE(buf, ksi) do {                                              \
        int koff = (ksi)*BK;                                                      \
        _Pragma("unroll")                                                         \
        for (int i=0;i<8;i++){                                                    \
            int chunk = tid + 256*i;                                              \
            int mat = chunk >> 10; int ch = chunk & 1023;                         \
            int row = ch >> 3, c16 = ch & 7;                                      \
            const __half* g = mat                                                 \
              ? Bw + (size_t)(bn*BN + row)*K + koff + c16*8                       \
              : Ap + (size_t)(bm*BM + row)*K + koff + c16*8;                      \
            uint32_t* s = (mat ? &Bs[(buf)*BN*SAW] : &As[(buf)*BM*SAW])           \
                          + row*SAW + c16*4;                                      \
            cp_async16(s, g);                                                     \
        }                                                                         \
        asm volatile("cp.async.commit_group;\n" ::);                              \
    } while(0)

    LOAD_TILE(0, 0);

    for (int ks = 0; ks < nK; ks++){
        asm volatile("cp.async.wait_group 0;\n" ::);
        __syncthreads();
        if (ks + 1 < nK) LOAD_TILE((ks+1)&1, ks+1);

        const uint32_t aB = aAddr0 + (ks&1)*ASTG;
        const uint32_t bB = bAddr0 + (ks&1)*BSTG;

        #pragma unroll
        for (int kst = 0; kst < 4; kst++){
            uint32_t bf[2][4];
            ldsm_x4(bf[0], bB + kst*32);
            ldsm_x4(bf[1], bB + 16*SAW*4 + kst*32);
            uint32_t af[4][4];
            #pragma unroll
            for (int mt=0; mt<4; mt++)
                ldsm_x4(af[mt], aB + mt*16*SAW*4 + kst*32);
            #pragma unroll
            for (int mt=0; mt<4; mt++)
                #pragma unroll
                for (int nt=0; nt<4; nt++)
                    mma16(acc[mt][nt], af[mt][0], af[mt][1], af[mt][2], af[mt][3],
                          bf[nt>>1][(nt&1)*2], bf[nt>>1][(nt&1)*2+1]);
        }
    }
    #undef LOAD_TILE

    if (MODE == 1){
        #pragma unroll
        for (int mt=0; mt<4; mt++){
            #pragma unroll
            for (int cc=0; cc<2; cc++){
                int gm  = bm*BM + wm*64 + mt*16 + qt + cc*8;
                int bwi = gm / NTOK;
                int tok = gm - bwi*NTOK;
                #pragma unroll
                for (int nt=0; nt<4; nt++){
                    int gn0 = bn*BN + wn*32 + nt*8 + 2*qr;
                    float v0 = acc[mt][nt][cc*2    ] + bias[gn0];
                    float v1 = acc[mt][nt][cc*2 + 1] + bias[gn0+1];
                    int which = gn0 / CDIM;
                    int rest  = gn0 - which*CDIM;
                    int h = rest >> 5, d = rest & 31;
                    if (which == 0){
                        v0 *= SCALE; v1 *= SCALE;
                        *(__half2*)&g_qk[(((size_t)bwi)*NH + h)*(NTOK*HD)
                                         + tok*HD + d] = __floats2half2_rn(v0, v1);
                    } else if (which == 1){
                        *(__half2*)&g_qk[(size_t)B_WIN*NH*NTOK*HD
                                         + (((size_t)bwi)*NH + h)*(NTOK*HD)
                                         + tok*HD + d] = __floats2half2_rn(v0, v1);
                    } else {
                        __half* vb = &g_vt[(((size_t)bwi)*NH + h)*(HD*64)];
                        vb[(size_t)d*64 + tok]     = __float2half_rn(v0);
                        vb[(size_t)(d+1)*64 + tok] = __float2half_rn(v1);
                    }
                }
            }
        }
    } else {
        #pragma unroll
        for (int mt=0; mt<4; mt++){
            #pragma unroll
            for (int cc=0; cc<2; cc++){
                int gm = bm*BM + wm*64 + mt*16 + qt + cc*8;
                #pragma unroll
                for (int nt=0; nt<4; nt++){
                    int gn0 = bn*BN + wn*32 + nt*8 + 2*qr;
                    out[(size_t)gm*N + gn0    ] = acc[mt][nt][cc*2    ] + bias[gn0];
                    out[(size_t)gm*N + gn0 + 1] = acc[mt][nt][cc*2 + 1] + bias[gn0+1];
                }
            }
        }
    }
}

/* ---------------- attention: one CTA per (b, h), ldmatrix + fp16 mma ------- */
__global__ void __launch_bounds__(128)
attn_kernel()
{
    /* word strides: qs/ksm 20, vsm/ps/cs 36 (all conflict-free by construction) */
    __shared__ uint32_t qs[64*20], ksm[64*20], vsm[32*36], ps[64*36], cs[64*36];

    const int b = blockIdx.y, h = blockIdx.x;
    const int tid = threadIdx.x;
    const int warp = tid >> 5, lane = tid & 31;
    const int qt = lane >> 2, qr = lane & 3;

    const size_t base = ((size_t)b*NH + h)*(NTOK*HD);
    const uint4* qg4 = (const uint4*)(g_qk + base);                              /* 49 x 4 */
    const uint4* kg4 = (const uint4*)(g_qk + (size_t)B_WIN*NH*NTOK*HD + base);
    const char*  vgc = (const char*)(g_vt + ((size_t)b*NH + h)*(HD*64));         /* 32 x 128B */
    const char*  cgc = (const char*)(g_cmbh + ((size_t)(b & (NWIN-1))*NH + h)*(64*64));

    /* v, cmb via cp.async (no predicates) */
    for (int i = tid; i < 256; i += 128){           /* v: 32 rows x 8 chunks */
        int r = i >> 3, c = i & 7;
        cp_async16(&vsm[r*36 + c*4], vgc + r*128 + c*16);
    }
    for (int i = tid; i < 512; i += 128){           /* cmb: 64 rows x 8 chunks */
        int r = i >> 3, c = i & 7;
        cp_async16(&cs[r*36 + c*4], cgc + r*128 + c*16);
    }
    asm volatile("cp.async.commit_group;\n" ::);

    /* q, k as uint4 with zero padding rows >= 49 */
    for (int i = tid; i < 256; i += 128){           /* 64 rows x 4 chunks */
        int r = i >> 2, c = i & 3;
        uint4 q = make_uint4(0,0,0,0), k = make_uint4(0,0,0,0);
        if (r < NTOK){ q = qg4[r*4 + c]; k = kg4[r*4 + c]; }
        *(uint4*)&qs [r*20 + c*4] = q;
        *(uint4*)&ksm[r*20 + c*4] = k;
    }
    asm volatile("cp.async.wait_group 0;\n" ::);
    __syncthreads();

    const int r0 = warp*16 + qt;
    const uint32_t s0q = (uint32_t)__cvta_generic_to_shared(qs);
    const uint32_t s0k = (uint32_t)__cvta_generic_to_shared(ksm);
    const uint32_t s0v = (uint32_t)__cvta_generic_to_shared(vsm);
    const uint32_t s0p = (uint32_t)__cvta_generic_to_shared(ps);

    const uint32_t aQ = s0q + ((warp*16 + (lane & 15))*20 + (lane >> 4)*4)*4;
    const uint32_t bK = s0k + (((lane & 7) + ((lane >> 4) & 1)*8)*20
                               + ((lane >> 3) & 1)*4)*4;
    const uint32_t aP = s0p + ((warp*16 + (lane & 15))*36 + (lane >> 4)*4)*4;
    const uint32_t bV = s0v + (((lane & 7) + ((lane >> 4) & 1)*8)*36
                               + ((lane >> 3) & 1)*4)*4;

    /* S = q @ k^T */
    float S[8][4];
    #pragma unroll
    for (int nt=0; nt<8; nt++)
        #pragma unroll
        for (int c=0; c<4; c++) S[nt][c] = 0.f;

    #pragma unroll
    for (int kst=0; kst<2; kst++){
        uint32_t af[4];
        ldsm_x4(af, aQ + kst*32);
        uint32_t bf[4][4];
        #pragma unroll
        for (int g=0; g<4; g++)
            ldsm_x4(bf[g], bK + g*16*20*4 + kst*32);
        #pragma unroll
        for (int nt=0; nt<8; nt++)
            mma16(S[nt], af[0], af[1], af[2], af[3],
                  bf[nt>>1][(nt&1)*2], bf[nt>>1][(nt&1)*2+1]);
    }

    /* + cmb (padding baked in, no branches) */
    #pragma unroll
    for (int nt=0; nt<8; nt++){
        #pragma unroll
        for (int hr=0; hr<2; hr++){
            int row = r0 + hr*8;
            uint32_t cw = cs[row*36 + nt*4 + qr];
            float2 cf = __half22float2(*(__half2*)&cw);
            S[nt][hr*2    ] += cf.x;
            S[nt][hr*2 + 1] += cf.y;
        }
    }

    /* softmax over m */
    float mx[2] = {-1e30f, -1e30f};
    #pragma unroll
    for (int nt=0; nt<8; nt++)
        #pragma unroll
        for (int c=0; c<4; c++)
            mx[c>>1] = fmaxf(mx[c>>1], S[nt][c]);
    #pragma unroll
    for (int o=1; o<4; o<<=1){
        mx[0] = fmaxf(mx[0], __shfl_xor_sync(0xffffffffu, mx[0], o));
        mx[1] = fmaxf(mx[1], __shfl_xor_sync(0xffffffffu, mx[1], o));
    }
    float sm[2] = {0.f, 0.f};
    #pragma unroll
    for (int nt=0; nt<8; nt++)
        #pragma unroll
        for (int c=0; c<4; c++){
            S[nt][c] = __expf(S[nt][c] - mx[c>>1]);
            sm[c>>1] += S[nt][c];
        }
    #pragma unroll
    for (int o=1; o<4; o<<=1){
        sm[0] += __shfl_xor_sync(0xffffffffu, sm[0], o);
        sm[1] += __shfl_xor_sync(0xffffffffu, sm[1], o);
    }

    /* P -> smem fp16 (warp-local slab) */
    #pragma unroll
    for (int nt=0; nt<8; nt++){
        #pragma unroll
        for (int hr=0; hr<2; hr++){
            int row = r0 + hr*8;
            ps[row*36 + nt*4 + qr] =
                h2u(__floats2half2_rn(S[nt][hr*2], S[nt][hr*2+1]));
        }
    }
    __syncwarp();

    /* O = P @ v */
    float O[4][4];
    #pragma unroll
    for (int nt=0; nt<4; nt++)
        #pragma unroll
        for (int c=0; c<4; c++) O[nt][c] = 0.f;

    #pragma unroll
    for (int ksx=0; ksx<4; ksx++){
        uint32_t af[4];
        ldsm_x4(af, aP + ksx*32);
        uint32_t bf[2][4];
        ldsm_x4(bf[0], bV + ksx*32);
        ldsm_x4(bf[1], bV + 16*36*4 + ksx*32);
        #pragma unroll
        for (int nt=0; nt<4; nt++)
            mma16(O[nt], af[0], af[1], af[2], af[3],
                  bf[nt>>1][(nt&1)*2], bf[nt>>1][(nt&1)*2+1]);
    }

    const float inv0 = 1.f / sm[0], inv1 = 1.f / sm[1];
    #pragma unroll
    for (int nt=0; nt<4; nt++){
        #pragma unroll
        for (int hr=0; hr<2; hr++){
            int row = r0 + hr*8;
            if (row < NTOK){
                int d = nt*8 + 2*qr;
                float inv = hr ? inv1 : inv0;
                *(__half2*)&g_atth[((size_t)b*NTOK + row)*CDIM + h*HD + d] =
                    __floats2half2_rn(O[nt][hr*2]*inv, O[nt][hr*2+1]*inv);
            }
        }
    }
}

extern "C" void kernel_launch(void* const* d_in, const int* in_sizes, int n_in,
                              void* d_out, int out_size)
{
    const float* x      = (const float*)d_in[0];
    const float* mask   = (const float*)d_in[1];
    const float* qkv_w  = (const float*)d_in[2];
    const float* qkv_b  = (const float*)d_in[3];
    const float* proj_w = (const float*)d_in[4];
    const float* proj_b = (const float*)d_in[5];
    const float* rpb    = (const float*)d_in[6];
    float* out = (float*)d_out;

    __half *xh, *wqkv, *wproj;
    cudaGetSymbolAddress((void**)&xh,    g_xh);
    cudaGetSymbolAddress((void**)&wqkv,  g_wqkv);
    cudaGetSymbolAddress((void**)&wproj, g_wproj);

    {
        int n1 = MTOT*CDIM/4;
        cvt_h_kernel<<<(n1+255)/256, 256>>>(x, xh, n1);
        int n2 = QKN*CDIM/4;
        cvt_h_kernel<<<(n2+255)/256, 256>>>(qkv_w, wqkv, n2);
        int n3 = CDIM*CDIM/4;
        cvt_h_kernel<<<(n3+255)/256, 256>>>(proj_w, wproj, n3);
        int nc = NWIN*NH*64*64;
        cmb_kernel<<<(nc+255)/256, 256>>>(mask, rpb);
    }

    const size_t smem_bytes = (size_t)2*(BM + BN)*SAW*sizeof(uint32_t); /* 73728 */
    cudaFuncSetAttribute(gemm_tn_kernel<0>,
                         cudaFuncAttributeMaxDynamicSharedMemorySize, (int)smem_bytes);
    cudaFuncSetAttribute(gemm_tn_kernel<1>,
                         cudaFuncAttributeMaxDynamicSharedMemorySize, (int)smem_bytes);

    gemm_tn_kernel<1><<<dim3(QKN/BN, MTOT/BM), 256, smem_bytes>>>(
        wqkv, qkv_b, nullptr, QKN, CDIM);

    attn_kernel<<<dim3(NH, B_WIN), 128>>>();

    gemm_tn_kernel<0><<<dim3(CDIM/BN, MTOT/BM), 256, smem_bytes>>>(
        wproj, proj_b, out, CDIM, CDIM);
}

// round 15
// speedup vs baseline: 2.9943x; 1.0172x over previous
#include <cuda_runtime.h>
#include <cuda_fp16.h>
#include <cstdint>

#define B_WIN 4096
#define NTOK  49
#define CDIM  384
#define NH    12
#define HD    32
#define NWIN  64
#define MTOT  (B_WIN*NTOK)          /* 200704 */
#define QKN   (3*CDIM)              /* 1152 */
#define SCALE 0.17677669529663687f  /* 32^-0.5 */

#define BM 128
#define BN 128
#define BK 64
#define SAW 36   /* gemm smem row stride in 32-bit words */

/* fp16 scratch */
__device__ __half g_xh  [(size_t)MTOT*CDIM];
__device__ __half g_atth[(size_t)MTOT*CDIM];
__device__ __half g_wqkv[(size_t)QKN*CDIM];
__device__ __half g_wproj[(size_t)CDIM*CDIM];
/* q,k: [2][B][H][49][32] half; v^T: [B][H][32 d][64 tok] half */
__device__ __half g_qk[(size_t)2*B_WIN*NH*NTOK*HD];
__device__ __half g_vt[(size_t)B_WIN*NH*HD*64];
/* combined rpb+mask, PADDED to 64x64 fp16: [64 w][12 h][64 row][64 m] */
__device__ __half g_cmbh[(size_t)NWIN*NH*64*64];

__device__ __forceinline__ void mma16(float c[4], uint32_t a0, uint32_t a1,
                                      uint32_t a2, uint32_t a3,
                                      uint32_t b0, uint32_t b1){
    asm volatile(
      "mma.sync.aligned.m16n8k16.row.col.f32.f16.f16.f32 "
      "{%0,%1,%2,%3},{%4,%5,%6,%7},{%8,%9},{%0,%1,%2,%3};\n"
      : "+f"(c[0]), "+f"(c[1]), "+f"(c[2]), "+f"(c[3])
      : "r"(a0), "r"(a1), "r"(a2), "r"(a3), "r"(b0), "r"(b1));
}
__device__ __forceinline__ void ldsm_x4(uint32_t r[4], uint32_t saddr){
    asm volatile("ldmatrix.sync.aligned.m8n8.x4.shared.b16 {%0,%1,%2,%3}, [%4];\n"
      : "=r"(r[0]), "=r"(r[1]), "=r"(r[2]), "=r"(r[3]) : "r"(saddr));
}
__device__ __forceinline__ void cp_async16(void* sdst, const void* gsrc){
    uint32_t s = (uint32_t)__cvta_generic_to_shared(sdst);
    asm volatile("cp.async.cg.shared.global [%0], [%1], 16;\n" :: "r"(s), "l"(gsrc));
}
__device__ __forceinline__ uint32_t h2u(__half2 h){ return *(uint32_t*)&h; }

/* -------- pre-pass: fp32 -> fp16 -------- */
__global__ void __launch_bounds__(256)
cvt_h_kernel(const float* __restrict__ in, __half* __restrict__ out, int n4)
{
    int i = blockIdx.x*256 + threadIdx.x;
    if (i >= n4) return;
    float4 v = ((const float4*)in)[i];
    ((__half2*)out)[2*i  ] = __floats2half2_rn(v.x, v.y);
    ((__half2*)out)[2*i+1] = __floats2half2_rn(v.z, v.w);
}

/* -------- pre-pass: padded fp16 cmb[w][h][row 64][m 64] -------- */
__global__ void __launch_bounds__(256)
cmb_kernel(const float* __restrict__ mask, const float* __restrict__ rpb)
{
    int i = blockIdx.x*256 + threadIdx.x;
    if (i >= NWIN*NH*64*64) return;
    int w  = i / (NH*64*64);
    int r1 = i - w*(NH*64*64);
    int h  = r1 / (64*64);
    int rm = r1 - h*(64*64);
    int row = rm >> 6, m = rm & 63;
    float val;
    if (m >= NTOK)        val = -30000.f;          /* kills softmax for pad cols */
    else if (row >= NTOK) val = 0.f;               /* unused rows */
    else {
        int ri = row/7, ci = row - ri*7;
        int rj = m  /7, cj = m   - rj*7;
        int idx = ((ri - rj + 6)*13 + (ci - cj + 6))*NH + h;
        val = rpb[idx] + mask[(size_t)w*NTOK*NTOK + row*NTOK + m];
    }
    g_cmbh[i] = __float2half_rn(val);
}

/* ---------------- GEMM: C = A(MxK) * B(NxK)^T + bias, fp16 in, fp32 acc ----
   MODE 0: A = g_atth, write fp32 out (proj)
   MODE 1: A = g_xh, scatter q*SCALE,k -> g_qk and v^T -> g_vt (fp16)         */
template<int MODE>
__global__ void __launch_bounds__(256, 2)
gemm_tn_kernel(const __half* __restrict__ Bw,
               const float* __restrict__ bias, float* __restrict__ out,
               int N, int K)
{
    extern __shared__ uint32_t smem[];
    uint32_t* As = smem;
    uint32_t* Bs = smem + 2*BM*SAW;

    const int bm = blockIdx.y, bn = blockIdx.x;
    const int tid = threadIdx.x;
    const int warp = tid >> 5, lane = tid & 31;
    const int wm = warp >> 2, wn = warp & 3;
    const int qt = lane >> 2, qr = lane & 3;

    const __half* Ap = (MODE == 0) ? g_atth : g_xh;

    float acc[4][4][4];
    #pragma unroll
    for (int i=0;i<4;i++)
      #pragma unroll
      for (int j=0;j<4;j++)
        #pragma unroll
        for (int c=0;c<4;c++) acc[i][j][c]=0.f;

    const int nK = K / BK;

    const uint32_t s0 = (uint32_t)__cvta_generic_to_shared(smem);
    const uint32_t aAddr0 = s0
        + ((wm*64 + (lane & 15))*SAW + (lane >> 4)*4)*4;
    const uint32_t bAddr0 = s0 + 2*BM*SAW*4
        + ((wn*32 + (lane & 7) + ((lane >> 4) & 1)*8)*SAW + ((lane >> 3) & 1)*4)*4;
    const uint32_t ASTG = BM*SAW*4;
    const uint32_t BSTG = BN*SAW*4;

    #define LOAD_TILE(buf, ksi) do {                                              \
        int koff = (ksi)*BK;                                                      \
        _Pragma("unroll")                                                         \
        for (int i=0;i<8;i++){                                                    \
            int chunk = tid + 256*i;                                              \
            int mat = chunk >> 10; int ch = chunk & 1023;                         \
            int row = ch >> 3, c16 = ch & 7;                                      \
            const __half* g = mat                                                 \
              ? Bw + (size_t)(bn*BN + row)*K + koff + c16*8                       \
              : Ap + (size_t)(bm*BM + row)*K + koff + c16*8;                      \
            uint32_t* s = (mat ? &Bs[(buf)*BN*SAW] : &As[(buf)*BM*SAW])           \
                          + row*SAW + c16*4;                                      \
            cp_async16(s, g);                                                     \
        }                                                                         \
        asm volatile("cp.async.commit_group;\n" ::);                              \
    } while(0)

    LOAD_TILE(0, 0);

    for (int ks = 0; ks < nK; ks++){
        asm volatile("cp.async.wait_group 0;\n" ::);
        __syncthreads();
        if (ks + 1 < nK) LOAD_TILE((ks+1)&1, ks+1);

        const uint32_t aB = aAddr0 + (ks&1)*ASTG;
        const uint32_t bB = bAddr0 + (ks&1)*BSTG;

        #pragma unroll
        for (int kst = 0; kst < 4; kst++){
            uint32_t bf[2][4];
            ldsm_x4(bf[0], bB + kst*32);
            ldsm_x4(bf[1], bB + 16*SAW*4 + kst*32);
            uint32_t af[4][4];
            #pragma unroll
            for (int mt=0; mt<4; mt++)
                ldsm_x4(af[mt], aB + mt*16*SAW*4 + kst*32);
            #pragma unroll
            for (int mt=0; mt<4; mt++)
                #pragma unroll
                for (int nt=0; nt<4; nt++)
                    mma16(acc[mt][nt], af[mt][0], af[mt][1], af[mt][2], af[mt][3],
                          bf[nt>>1][(nt&1)*2], bf[nt>>1][(nt&1)*2+1]);
        }
    }
    #undef LOAD_TILE

    if (MODE == 1){
        #pragma unroll
        for (int mt=0; mt<4; mt++){
            #pragma unroll
            for (int cc=0; cc<2; cc++){
                int gm  = bm*BM + wm*64 + mt*16 + qt + cc*8;
                int bwi = gm / NTOK;
                int tok = gm - bwi*NTOK;
                #pragma unroll
                for (int nt=0; nt<4; nt++){
                    int gn0 = bn*BN + wn*32 + nt*8 + 2*qr;
                    float v0 = acc[mt][nt][cc*2    ] + bias[gn0];
                    float v1 = acc[mt][nt][cc*2 + 1] + bias[gn0+1];
                    int which = gn0 / CDIM;
                    int rest  = gn0 - which*CDIM;
                    int h = rest >> 5, d = rest & 31;
                    if (which == 0){
                        v0 *= SCALE; v1 *= SCALE;
                        *(__half2*)&g_qk[(((size_t)bwi)*NH + h)*(NTOK*HD)
                                         + tok*HD + d] = __floats2half2_rn(v0, v1);
                    } else if (which == 1){
                        *(__half2*)&g_qk[(size_t)B_WIN*NH*NTOK*HD
                                         + (((size_t)bwi)*NH + h)*(NTOK*HD)
                                         + tok*HD + d] = __floats2half2_rn(v0, v1);
                    } else {
                        __half* vb = &g_vt[(((size_t)bwi)*NH + h)*(HD*64)];
                        vb[(size_t)d*64 + tok]     = __float2half_rn(v0);
                        vb[(size_t)(d+1)*64 + tok] = __float2half_rn(v1);
                    }
                }
            }
        }
    } else {
        #pragma unroll
        for (int mt=0; mt<4; mt++){
            #pragma unroll
            for (int cc=0; cc<2; cc++){
                int gm = bm*BM + wm*64 + mt*16 + qt + cc*8;
                #pragma unroll
                for (int nt=0; nt<4; nt++){
                    int gn0 = bn*BN + wn*32 + nt*8 + 2*qr;
                    out[(size_t)gm*N + gn0    ] = acc[mt][nt][cc*2    ] + bias[gn0];
                    out[(size_t)gm*N + gn0 + 1] = acc[mt][nt][cc*2 + 1] + bias[gn0+1];
                }
            }
        }
    }
}

/* ---------------- attention: one CTA per (b, h), ldmatrix + fp16 mma -------
   smem cut: P tile aliases the cmb tile (cmb fully consumed into registers
   before P is written; both touch only the warp's own 16-row slab).          */
__global__ void __launch_bounds__(128, 8)
attn_kernel()
{
    /* word strides: qs/ksm 20, vsm/csps 36 (conflict-free by construction) */
    __shared__ uint32_t qs[64*20], ksm[64*20], vsm[32*36], csps[64*36];

    const int b = blockIdx.y, h = blockIdx.x;
    const int tid = threadIdx.x;
    const int warp = tid >> 5, lane = tid & 31;
    const int qt = lane >> 2, qr = lane & 3;

    const size_t base = ((size_t)b*NH + h)*(NTOK*HD);
    const uint4* qg4 = (const uint4*)(g_qk + base);
    const uint4* kg4 = (const uint4*)(g_qk + (size_t)B_WIN*NH*NTOK*HD + base);
    const char*  vgc = (const char*)(g_vt + ((size_t)b*NH + h)*(HD*64));
    const char*  cgc = (const char*)(g_cmbh + ((size_t)(b & (NWIN-1))*NH + h)*(64*64));

    for (int i = tid; i < 256; i += 128){           /* v: 32 rows x 8 chunks */
        int r = i >> 3, c = i & 7;
        cp_async16(&vsm[r*36 + c*4], vgc + r*128 + c*16);
    }
    for (int i = tid; i < 512; i += 128){           /* cmb: 64 rows x 8 chunks */
        int r = i >> 3, c = i & 7;
        cp_async16(&csps[r*36 + c*4], cgc + r*128 + c*16);
    }
    asm volatile("cp.async.commit_group;\n" ::);

    for (int i = tid; i < 256; i += 128){           /* q,k: 64 rows x 4 chunks */
        int r = i >> 2, c = i & 3;
        uint4 q = make_uint4(0,0,0,0), k = make_uint4(0,0,0,0);
        if (r < NTOK){ q = qg4[r*4 + c]; k = kg4[r*4 + c]; }
        *(uint4*)&qs [r*20 + c*4] = q;
        *(uint4*)&ksm[r*20 + c*4] = k;
    }
    asm volatile("cp.async.wait_group 0;\n" ::);
    __syncthreads();

    const int r0 = warp*16 + qt;
    const uint32_t s0q = (uint32_t)__cvta_generic_to_shared(qs);
    const uint32_t s0k = (uint32_t)__cvta_generic_to_shared(ksm);
    const uint32_t s0v = (uint32_t)__cvta_generic_to_shared(vsm);
    const uint32_t s0p = (uint32_t)__cvta_generic_to_shared(csps);

    const uint32_t aQ = s0q + ((warp*16 + (lane & 15))*20 + (lane >> 4)*4)*4;
    const uint32_t bK = s0k + (((lane & 7) + ((lane >> 4) & 1)*8)*20
                               + ((lane >> 3) & 1)*4)*4;
    const uint32_t aP = s0p + ((warp*16 + (lane & 15))*36 + (lane >> 4)*4)*4;
    const uint32_t bV = s0v + (((lane & 7) + ((lane >> 4) & 1)*8)*36
                               + ((lane >> 3) & 1)*4)*4;

    /* S = q @ k^T */
    float S[8][4];
    #pragma unroll
    for (int nt=0; nt<8; nt++)
        #pragma unroll
        for (int c=0; c<4; c++) S[nt][c] = 0.f;

    #pragma unroll
    for (int kst=0; kst<2; kst++){
        uint32_t af[4];
        ldsm_x4(af, aQ + kst*32);
        uint32_t bf[4][4];
        #pragma unroll
        for (int g=0; g<4; g++)
            ldsm_x4(bf[g], bK + g*16*20*4 + kst*32);
        #pragma unroll
        for (int nt=0; nt<8; nt++)
            mma16(S[nt], af[0], af[1], af[2], af[3],
                  bf[nt>>1][(nt&1)*2], bf[nt>>1][(nt&1)*2+1]);
    }

    /* + cmb (padding baked in; consumed fully before P overwrites the tile) */
    #pragma unroll
    for (int nt=0; nt<8; nt++){
        #pragma unroll
        for (int hr=0; hr<2; hr++){
            int row = r0 + hr*8;
            uint32_t cw = csps[row*36 + nt*4 + qr];
            float2 cf = __half22float2(*(__half2*)&cw);
            S[nt][hr*2    ] += cf.x;
            S[nt][hr*2 + 1] += cf.y;
        }
    }

    /* softmax over m */
    float mx[2] = {-1e30f, -1e30f};
    #pragma unroll
    for (int nt=0; nt<8; nt++)
        #pragma unroll
        for (int c=0; c<4; c++)
            mx[c>>1] = fmaxf(mx[c>>1], S[nt][c]);
    #pragma unroll
    for (int o=1; o<4; o<<=1){
        mx[0] = fmaxf(mx[0], __shfl_xor_sync(0xffffffffu, mx[0], o));
        mx[1] = fmaxf(mx[1], __shfl_xor_sync(0xffffffffu, mx[1], o));
    }
    float sm[2] = {0.f, 0.f};
    #pragma unroll
    for (int nt=0; nt<8; nt++)
        #pragma unroll
        for (int c=0; c<4; c++){
            S[nt][c] = __expf(S[nt][c] - mx[c>>1]);
            sm[c>>1] += S[nt][c];
        }
    #pragma unroll
    for (int o=1; o<4; o<<=1){
        sm[0] += __shfl_xor_sync(0xffffffffu, sm[0], o);
        sm[1] += __shfl_xor_sync(0xffffffffu, sm[1], o);
    }

    /* P -> smem fp16, overwriting this warp's cmb slab (already consumed) */
    #pragma unroll
    for (int nt=0; nt<8; nt++){
        #pragma unroll
        for (int hr=0; hr<2; hr++){
            int row = r0 + hr*8;
            csps[row*36 + nt*4 + qr] =
                h2u(__floats2half2_rn(S[nt][hr*2], S[nt][hr*2+1]));
        }
    }
    __syncwarp();

    /* O = P @ v */
    float O[4][4];
    #pragma unroll
    for (int nt=0; nt<4; nt++)
        #pragma unroll
        for (int c=0; c<4; c++) O[nt][c] = 0.f;

    #pragma unroll
    for (int ksx=0; ksx<4; ksx++){
        uint32_t af[4];
        ldsm_x4(af, aP + ksx*32);
        uint32_t bf[2][4];
        ldsm_x4(bf[0], bV + ksx*32);
        ldsm_x4(bf[1], bV + 16*36*4 + ksx*32);
        #pragma unroll
        for (int nt=0; nt<4; nt++)
            mma16(O[nt], af[0], af[1], af[2], af[3],
                  bf[nt>>1][(nt&1)*2], bf[nt>>1][(nt&1)*2+1]);
    }

    const float inv0 = 1.f / sm[0], inv1 = 1.f / sm[1];
    #pragma unroll
    for (int nt=0; nt<4; nt++){
        #pragma unroll
        for (int hr=0; hr<2; hr++){
            int row = r0 + hr*8;
            if (row < NTOK){
                int d = nt*8 + 2*qr;
                float inv = hr ? inv1 : inv0;
                *(__half2*)&g_atth[((size_t)b*NTOK + row)*CDIM + h*HD + d] =
                    __floats2half2_rn(O[nt][hr*2]*inv, O[nt][hr*2+1]*inv);
            }
        }
    }
}

extern "C" void kernel_launch(void* const* d_in, const int* in_sizes, int n_in,
                              void* d_out, int out_size)
{
    const float* x      = (const float*)d_in[0];
    const float* mask   = (const float*)d_in[1];
    const float* qkv_w  = (const float*)d_in[2];
    const float* qkv_b  = (const float*)d_in[3];
    const float* proj_w = (const float*)d_in[4];
    const float* proj_b = (const float*)d_in[5];
    const float* rpb    = (const float*)d_in[6];
    float* out = (float*)d_out;

    __half *xh, *wqkv, *wproj;
    cudaGetSymbolAddress((void**)&xh,    g_xh);
    cudaGetSymbolAddress((void**)&wqkv,  g_wqkv);
    cudaGetSymbolAddress((void**)&wproj, g_wproj);

    {
        int n1 = MTOT*CDIM/4;
        cvt_h_kernel<<<(n1+255)/256, 256>>>(x, xh, n1);
        int n2 = QKN*CDIM/4;
        cvt_h_kernel<<<(n2+255)/256, 256>>>(qkv_w, wqkv, n2);
        int n3 = CDIM*CDIM/4;
        cvt_h_kernel<<<(n3+255)/256, 256>>>(proj_w, wproj, n3);
        int nc = NWIN*NH*64*64;
        cmb_kernel<<<(nc+255)/256, 256>>>(mask, rpb);
    }

    const size_t smem_bytes = (size_t)2*(BM + BN)*SAW*sizeof(uint32_t); /* 73728 */
    cudaFuncSetAttribute(gemm_tn_kernel<0>,
                         cudaFuncAttributeMaxDynamicSharedMemorySize, (int)smem_bytes);
    cudaFuncSetAttribute(gemm_tn_kernel<1>,
                         cudaFuncAttributeMaxDynamicSharedMemorySize, (int)smem_bytes);

    gemm_tn_kernel<1><<<dim3(QKN/BN, MTOT/BM), 256, smem_bytes>>>(
        wqkv, qkv_b, nullptr, QKN, CDIM);

    attn_kernel<<<dim3(NH, B_WIN), 128>>>();

    gemm_tn_kernel<0><<<dim3(CDIM/BN, MTOT/BM), 256, smem_bytes>>>(
        wproj, proj_b, out, CDIM, CDIM);
}

// round 16
// speedup vs baseline: 3.1373x; 1.0478x over previous
#include <cuda_runtime.h>
#include <cuda_fp16.h>
#include <cstdint>

#define B_WIN 4096
#define NTOK  49
#define CDIM  384
#define NH    12
#define HD    32
#define NWIN  64
#define MTOT  (B_WIN*NTOK)          /* 200704 */
#define QKN   (3*CDIM)              /* 1152 */
#define SCALE 0.17677669529663687f  /* 32^-0.5 */

#define BM 128
#define BN 128
#define BK 64
#define SAW 36   /* gemm smem row stride in 32-bit words */

/* fp16 scratch */
__device__ __half g_xh  [(size_t)MTOT*CDIM];
__device__ __half g_atth[(size_t)MTOT*CDIM];
__device__ __half g_wqkv[(size_t)QKN*CDIM];
__device__ __half g_wproj[(size_t)CDIM*CDIM];
/* q,k,v: [3][B][H][64][32] half, rows 49-63 permanently zero (zero-init) */
__device__ __half g_qkv3[(size_t)3*B_WIN*NH*64*HD];
/* combined rpb+mask, PADDED to 64x64 fp16: [64 w][12 h][64 row][64 m] */
__device__ __half g_cmbh[(size_t)NWIN*NH*64*64];

__device__ __forceinline__ void mma16(float c[4], uint32_t a0, uint32_t a1,
                                      uint32_t a2, uint32_t a3,
                                      uint32_t b0, uint32_t b1){
    asm volatile(
      "mma.sync.aligned.m16n8k16.row.col.f32.f16.f16.f32 "
      "{%0,%1,%2,%3},{%4,%5,%6,%7},{%8,%9},{%0,%1,%2,%3};\n"
      : "+f"(c[0]), "+f"(c[1]), "+f"(c[2]), "+f"(c[3])
      : "r"(a0), "r"(a1), "r"(a2), "r"(a3), "r"(b0), "r"(b1));
}
__device__ __forceinline__ void ldsm_x4(uint32_t r[4], uint32_t saddr){
    asm volatile("ldmatrix.sync.aligned.m8n8.x4.shared.b16 {%0,%1,%2,%3}, [%4];\n"
      : "=r"(r[0]), "=r"(r[1]), "=r"(r[2]), "=r"(r[3]) : "r"(saddr));
}
__device__ __forceinline__ void ldsm_x4_t(uint32_t r[4], uint32_t saddr){
    asm volatile("ldmatrix.sync.aligned.m8n8.x4.trans.shared.b16 {%0,%1,%2,%3}, [%4];\n"
      : "=r"(r[0]), "=r"(r[1]), "=r"(r[2]), "=r"(r[3]) : "r"(saddr));
}
__device__ __forceinline__ void cp_async16(void* sdst, const void* gsrc){
    uint32_t s = (uint32_t)__cvta_generic_to_shared(sdst);
    asm volatile("cp.async.cg.shared.global [%0], [%1], 16;\n" :: "r"(s), "l"(gsrc));
}
__device__ __forceinline__ uint32_t h2u(__half2 h){ return *(uint32_t*)&h; }

/* -------- pre-pass: fp32 -> fp16 -------- */
__global__ void __launch_bounds__(256)
cvt_h_kernel(const float* __restrict__ in, __half* __restrict__ out, int n4)
{
    int i = blockIdx.x*256 + threadIdx.x;
    if (i >= n4) return;
    float4 v = ((const float4*)in)[i];
    ((__half2*)out)[2*i  ] = __floats2half2_rn(v.x, v.y);
    ((__half2*)out)[2*i+1] = __floats2half2_rn(v.z, v.w);
}

/* -------- pre-pass: padded fp16 cmb[w][h][row 64][m 64] -------- */
__global__ void __launch_bounds__(256)
cmb_kernel(const float* __restrict__ mask, const float* __restrict__ rpb)
{
    int i = blockIdx.x*256 + threadIdx.x;
    if (i >= NWIN*NH*64*64) return;
    int w  = i / (NH*64*64);
    int r1 = i - w*(NH*64*64);
    int h  = r1 / (64*64);
    int rm = r1 - h*(64*64);
    int row = rm >> 6, m = rm & 63;
    float val;
    if (m >= NTOK)        val = -30000.f;          /* kills softmax for pad cols */
    else if (row >= NTOK) val = 0.f;               /* unused rows */
    else {
        int ri = row/7, ci = row - ri*7;
        int rj = m  /7, cj = m   - rj*7;
        int idx = ((ri - rj + 6)*13 + (ci - cj + 6))*NH + h;
        val = rpb[idx] + mask[(size_t)w*NTOK*NTOK + row*NTOK + m];
    }
    g_cmbh[i] = __float2half_rn(val);
}

/* ---------------- GEMM: C = A(MxK) * B(NxK)^T + bias, fp16 in, fp32 acc ----
   MODE 0: A = g_atth, write fp32 out (proj)
   MODE 1: A = g_xh, scatter q*SCALE,k,v (all coalesced) -> g_qkv3 (fp16)     */
template<int MODE>
__global__ void __launch_bounds__(256, 2)
gemm_tn_kernel(const __half* __restrict__ Bw,
               const float* __restrict__ bias, float* __restrict__ out,
               int N, int K)
{
    extern __shared__ uint32_t smem[];
    uint32_t* As = smem;
    uint32_t* Bs = smem + 2*BM*SAW;

    const int bm = blockIdx.y, bn = blockIdx.x;
    const int tid = threadIdx.x;
    const int warp = tid >> 5, lane = tid & 31;
    const int wm = warp >> 2, wn = warp & 3;
    const int qt = lane >> 2, qr = lane & 3;

    const __half* Ap = (MODE == 0) ? g_atth : g_xh;

    float acc[4][4][4];
    #pragma unroll
    for (int i=0;i<4;i++)
      #pragma unroll
      for (int j=0;j<4;j++)
        #pragma unroll
        for (int c=0;c<4;c++) acc[i][j][c]=0.f;

    const int nK = K / BK;

    const uint32_t s0 = (uint32_t)__cvta_generic_to_shared(smem);
    const uint32_t aAddr0 = s0
        + ((wm*64 + (lane & 15))*SAW + (lane >> 4)*4)*4;
    const uint32_t bAddr0 = s0 + 2*BM*SAW*4
        + ((wn*32 + (lane & 7) + ((lane >> 4) & 1)*8)*SAW + ((lane >> 3) & 1)*4)*4;
    const uint32_t ASTG = BM*SAW*4;
    const uint32_t BSTG = BN*SAW*4;

    #define LOAD_TILE(buf, ksi) do {                                              \
        int koff = (ksi)*BK;                                                      \
        _Pragma("unroll")                                                         \
        for (int i=0;i<8;i++){                                                    \
            int chunk = tid + 256*i;                                              \
            int mat = chunk >> 10; int ch = chunk & 1023;                         \
            int row = ch >> 3, c16 = ch & 7;                                      \
            const __half* g = mat                                                 \
              ? Bw + (size_t)(bn*BN + row)*K + koff + c16*8                       \
              : Ap + (size_t)(bm*BM + row)*K + koff + c16*8;                      \
            uint32_t* s = (mat ? &Bs[(buf)*BN*SAW] : &As[(buf)*BM*SAW])           \
                          + row*SAW + c16*4;                                      \
            cp_async16(s, g);                                                     \
        }                                                                         \
        asm volatile("cp.async.commit_group;\n" ::);                              \
    } while(0)

    LOAD_TILE(0, 0);

    for (int ks = 0; ks < nK; ks++){
        asm volatile("cp.async.wait_group 0;\n" ::);
        __syncthreads();
        if (ks + 1 < nK) LOAD_TILE((ks+1)&1, ks+1);

        const uint32_t aB = aAddr0 + (ks&1)*ASTG;
        const uint32_t bB = bAddr0 + (ks&1)*BSTG;

        #pragma unroll
        for (int kst = 0; kst < 4; kst++){
            uint32_t bf[2][4];
            ldsm_x4(bf[0], bB + kst*32);
            ldsm_x4(bf[1], bB + 16*SAW*4 + kst*32);
            uint32_t af[4][4];
            #pragma unroll
            for (int mt=0; mt<4; mt++)
                ldsm_x4(af[mt], aB + mt*16*SAW*4 + kst*32);
            #pragma unroll
            for (int mt=0; mt<4; mt++)
                #pragma unroll
                for (int nt=0; nt<4; nt++)
                    mma16(acc[mt][nt], af[mt][0], af[mt][1], af[mt][2], af[mt][3],
                          bf[nt>>1][(nt&1)*2], bf[nt>>1][(nt&1)*2+1]);
        }
    }
    #undef LOAD_TILE

    if (MODE == 1){
        #pragma unroll
        for (int mt=0; mt<4; mt++){
            #pragma unroll
            for (int cc=0; cc<2; cc++){
                int gm  = bm*BM + wm*64 + mt*16 + qt + cc*8;
                int bwi = gm / NTOK;
                int tok = gm - bwi*NTOK;
                #pragma unroll
                for (int nt=0; nt<4; nt++){
                    int gn0 = bn*BN + wn*32 + nt*8 + 2*qr;
                    float v0 = acc[mt][nt][cc*2    ] + bias[gn0];
                    float v1 = acc[mt][nt][cc*2 + 1] + bias[gn0+1];
                    int which = gn0 / CDIM;
                    int rest  = gn0 - which*CDIM;
                    int h = rest >> 5, d = rest & 31;
                    float sc = (which == 0) ? SCALE : 1.f;
                    /* all three coalesced: [which][b][h][tok][d], 64-row blocks */
                    __half* dst = g_qkv3
                        + ((size_t)which*B_WIN*NH + (size_t)bwi*NH + h)*(64*HD)
                        + tok*HD + d;
                    *(__half2*)dst = __floats2half2_rn(v0*sc, v1*sc);
                }
            }
        }
    } else {
        #pragma unroll
        for (int mt=0; mt<4; mt++){
            #pragma unroll
            for (int cc=0; cc<2; cc++){
                int gm = bm*BM + wm*64 + mt*16 + qt + cc*8;
                #pragma unroll
                for (int nt=0; nt<4; nt++){
                    int gn0 = bn*BN + wn*32 + nt*8 + 2*qr;
                    out[(size_t)gm*N + gn0    ] = acc[mt][nt][cc*2    ] + bias[gn0];
                    out[(size_t)gm*N + gn0 + 1] = acc[mt][nt][cc*2 + 1] + bias[gn0+1];
                }
            }
        }
    }
}

/* ---------------- attention: one CTA per (b, h) --------------------------
   All tiles via cp.async (q/k/v have zero-padded rows 49-63 in gmem).
   V stored row-major [tok][d]; transposed at load via ldmatrix.x4.trans.
   P tile aliases cmb tile (cmb fully consumed before P written).            */
__global__ void __launch_bounds__(128, 8)
attn_kernel()
{
    /* word strides: qs/ksm/vsm 20, csps 36 (conflict-free by construction) */
    __shared__ uint32_t qs[64*20], ksm[64*20], vsm[64*20], csps[64*36];

    const int b = blockIdx.y, h = blockIdx.x;
    const int tid = threadIdx.x;
    const int warp = tid >> 5, lane = tid & 31;
    const int qt = lane >> 2, qr = lane & 3;

    const size_t blk = ((size_t)b*NH + h)*(64*HD);
    const char* qgc = (const char*)(g_qkv3 + blk);
    const char* kgc = (const char*)(g_qkv3 + (size_t)B_WIN*NH*64*HD   + blk);
    const char* vgc = (const char*)(g_qkv3 + (size_t)2*B_WIN*NH*64*HD + blk);
    const char* cgc = (const char*)(g_cmbh + ((size_t)(b & (NWIN-1))*NH + h)*(64*64));

    /* q,k,v: 64 rows x 4 chunks of 16B (row = 64B data, smem stride 80B) */
    for (int i = tid; i < 256; i += 128){
        int r = i >> 2, c = i & 3;
        cp_async16(&qs [r*20 + c*4], qgc + r*64 + c*16);
        cp_async16(&ksm[r*20 + c*4], kgc + r*64 + c*16);
        cp_async16(&vsm[r*20 + c*4], vgc + r*64 + c*16);
    }
    /* cmb: 64 rows x 8 chunks (row = 128B data, smem stride 144B) */
    for (int i = tid; i < 512; i += 128){
        int r = i >> 3, c = i & 7;
        cp_async16(&csps[r*36 + c*4], cgc + r*128 + c*16);
    }
    asm volatile("cp.async.commit_group;\n" ::);
    asm volatile("cp.async.wait_group 0;\n" ::);
    __syncthreads();

    const int r0 = warp*16 + qt;
    const uint32_t s0q = (uint32_t)__cvta_generic_to_shared(qs);
    const uint32_t s0k = (uint32_t)__cvta_generic_to_shared(ksm);
    const uint32_t s0v = (uint32_t)__cvta_generic_to_shared(vsm);
    const uint32_t s0p = (uint32_t)__cvta_generic_to_shared(csps);

    const uint32_t aQ = s0q + ((warp*16 + (lane & 15))*20 + (lane >> 4)*4)*4;
    const uint32_t bK = s0k + (((lane & 7) + ((lane >> 4) & 1)*8)*20
                               + ((lane >> 3) & 1)*4)*4;
    const uint32_t aP = s0p + ((warp*16 + (lane & 15))*36 + (lane >> 4)*4)*4;
    /* V trans-load: rows k = lane&15, n-halfblock (lane>>4)*16B */
    const uint32_t bV = s0v + (((lane & 15))*20 + (lane >> 4)*4)*4;

    /* S = q @ k^T */
    float S[8][4];
    #pragma unroll
    for (int nt=0; nt<8; nt++)
        #pragma unroll
        for (int c=0; c<4; c++) S[nt][c] = 0.f;

    #pragma unroll
    for (int kst=0; kst<2; kst++){
        uint32_t af[4];
        ldsm_x4(af, aQ + kst*32);
        uint32_t bf[4][4];
        #pragma unroll
        for (int g=0; g<4; g++)
            ldsm_x4(bf[g], bK + g*16*20*4 + kst*32);
        #pragma unroll
        for (int nt=0; nt<8; nt++)
            mma16(S[nt], af[0], af[1], af[2], af[3],
                  bf[nt>>1][(nt&1)*2], bf[nt>>1][(nt&1)*2+1]);
    }

    /* + cmb (padding baked in; consumed fully before P overwrites the tile) */
    #pragma unroll
    for (int nt=0; nt<8; nt++){
        #pragma unroll
        for (int hr=0; hr<2; hr++){
            int row = r0 + hr*8;
            uint32_t cw = csps[row*36 + nt*4 + qr];
            float2 cf = __half22float2(*(__half2*)&cw);
            S[nt][hr*2    ] += cf.x;
            S[nt][hr*2 + 1] += cf.y;
        }
    }

    /* softmax over m */
    float mx[2] = {-1e30f, -1e30f};
    #pragma unroll
    for (int nt=0; nt<8; nt++)
        #pragma unroll
        for (int c=0; c<4; c++)
            mx[c>>1] = fmaxf(mx[c>>1], S[nt][c]);
    #pragma unroll
    for (int o=1; o<4; o<<=1){
        mx[0] = fmaxf(mx[0], __shfl_xor_sync(0xffffffffu, mx[0], o));
        mx[1] = fmaxf(mx[1], __shfl_xor_sync(0xffffffffu, mx[1], o));
    }
    float sm[2] = {0.f, 0.f};
    #pragma unroll
    for (int nt=0; nt<8; nt++)
        #pragma unroll
        for (int c=0; c<4; c++){
            S[nt][c] = __expf(S[nt][c] - mx[c>>1]);
            sm[c>>1] += S[nt][c];
        }
    #pragma unroll
    for (int o=1; o<4; o<<=1){
        sm[0] += __shfl_xor_sync(0xffffffffu, sm[0], o);
        sm[1] += __shfl_xor_sync(0xffffffffu, sm[1], o);
    }

    /* P -> smem fp16, overwriting this warp's cmb slab (already consumed) */
    #pragma unroll
    for (int nt=0; nt<8; nt++){
        #pragma unroll
        for (int hr=0; hr<2; hr++){
            int row = r0 + hr*8;
            csps[row*36 + nt*4 + qr] =
                h2u(__floats2half2_rn(S[nt][hr*2], S[nt][hr*2+1]));
        }
    }
    __syncwarp();

    /* O = P @ v  (V trans-loaded from [tok][d] layout) */
    float O[4][4];
    #pragma unroll
    for (int nt=0; nt<4; nt++)
        #pragma unroll
        for (int c=0; c<4; c++) O[nt][c] = 0.f;

    #pragma unroll
    for (int ksx=0; ksx<4; ksx++){
        uint32_t af[4];
        ldsm_x4(af, aP + ksx*32);
        uint32_t bf[2][4];
        ldsm_x4_t(bf[0], bV + ksx*16*20*4);        /* d 0-15  */
        ldsm_x4_t(bf[1], bV + ksx*16*20*4 + 32);   /* d 16-31 */
        #pragma unroll
        for (int nt=0; nt<4; nt++)
            mma16(O[nt], af[0], af[1], af[2], af[3],
                  bf[nt>>1][(nt&1)*2], bf[nt>>1][(nt&1)*2+1]);
    }

    const float inv0 = 1.f / sm[0], inv1 = 1.f / sm[1];
    #pragma unroll
    for (int nt=0; nt<4; nt++){
        #pragma unroll
        for (int hr=0; hr<2; hr++){
            int row = r0 + hr*8;
            if (row < NTOK){
                int d = nt*8 + 2*qr;
                float inv = hr ? inv1 : inv0;
                *(__half2*)&g_atth[((size_t)b*NTOK + row)*CDIM + h*HD + d] =
                    __floats2half2_rn(O[nt][hr*2]*inv, O[nt][hr*2+1]*inv);
            }
        }
    }
}

extern "C" void kernel_launch(void* const* d_in, const int* in_sizes, int n_in,
                              void* d_out, int out_size)
{
    const float* x      = (const float*)d_in[0];
    const float* mask   = (const float*)d_in[1];
    const float* qkv_w  = (const float*)d_in[2];
    const float* qkv_b  = (const float*)d_in[3];
    const float* proj_w = (const float*)d_in[4];
    const float* proj_b = (const float*)d_in[5];
    const float* rpb    = (const float*)d_in[6];
    float* out = (float*)d_out;

    __half *xh, *wqkv, *wproj;
    cudaGetSymbolAddress((void**)&xh,    g_xh);
    cudaGetSymbolAddress((void**)&wqkv,  g_wqkv);
    cudaGetSymbolAddress((void**)&wproj, g_wproj);

    {
        int n1 = MTOT*CDIM/4;
        cvt_h_kernel<<<(n1+255)/256, 256>>>(x, xh, n1);
        int n2 = QKN*CDIM/4;
        cvt_h_kernel<<<(n2+255)/256, 256>>>(qkv_w, wqkv, n2);
        int n3 = CDIM*CDIM/4;
        cvt_h_kernel<<<(n3+255)/256, 256>>>(proj_w, wproj, n3);
        int nc = NWIN*NH*64*64;
        cmb_kernel<<<(nc+255)/256, 256>>>(mask, rpb);
    }

    const size_t smem_bytes = (size_t)2*(BM + BN)*SAW*sizeof(uint32_t); /* 73728 */
    cudaFuncSetAttribute(gemm_tn_kernel<0>,
                         cudaFuncAttributeMaxDynamicSharedMemorySize, (int)smem_bytes);
    cudaFuncSetAttribute(gemm_tn_kernel<1>,
                         cudaFuncAttributeMaxDynamicSharedMemorySize, (int)smem_bytes);

    gemm_tn_kernel<1><<<dim3(QKN/BN, MTOT/BM), 256, smem_bytes>>>(
        wqkv, qkv_b, nullptr, QKN, CDIM);

    attn_kernel<<<dim3(NH, B_WIN), 128>>>();

    gemm_tn_kernel<0><<<dim3(CDIM/BN, MTOT/BM), 256, smem_bytes>>>(
        wproj, proj_b, out, CDIM, CDIM);
}

// round 17
// speedup vs baseline: 3.3711x; 1.0745x over previous
#include <cuda_runtime.h>
#include <cuda_fp16.h>
#include <cstdint>

#define B_WIN 4096
#define NTOK  49
#define CDIM  384
#define NH    12
#define HD    32
#define NWIN  64
#define MTOT  (B_WIN*NTOK)          /* 200704 */
#define QKN   (3*CDIM)              /* 1152 */
#define SCALE 0.17677669529663687f  /* 32^-0.5 */

#define BM 128
#define BN 128
#define BK 64
#define NKT 6    /* K = 384 = 6 * BK for BOTH gemms (compile-time) */
#define SAW 36   /* gemm smem row stride in 32-bit words */
#define NSTG 3   /* cp.async pipeline stages */

/* fp16 scratch */
__device__ __half g_xh  [(size_t)MTOT*CDIM];
__device__ __half g_atth[(size_t)MTOT*CDIM];
__device__ __half g_wqkv[(size_t)QKN*CDIM];
__device__ __half g_wproj[(size_t)CDIM*CDIM];
/* q,k,v: [3][B][H][64][32] half, rows 49-63 permanently zero (zero-init) */
__device__ __half g_qkv3[(size_t)3*B_WIN*NH*64*HD];
/* combined rpb+mask, PADDED to 64x64 fp16: [64 w][12 h][64 row][64 m] */
__device__ __half g_cmbh[(size_t)NWIN*NH*64*64];

__device__ __forceinline__ void mma16(float c[4], uint32_t a0, uint32_t a1,
                                      uint32_t a2, uint32_t a3,
                                      uint32_t b0, uint32_t b1){
    asm volatile(
      "mma.sync.aligned.m16n8k16.row.col.f32.f16.f16.f32 "
      "{%0,%1,%2,%3},{%4,%5,%6,%7},{%8,%9},{%0,%1,%2,%3};\n"
      : "+f"(c[0]), "+f"(c[1]), "+f"(c[2]), "+f"(c[3])
      : "r"(a0), "r"(a1), "r"(a2), "r"(a3), "r"(b0), "r"(b1));
}
__device__ __forceinline__ void ldsm_x4(uint32_t r[4], uint32_t saddr){
    asm volatile("ldmatrix.sync.aligned.m8n8.x4.shared.b16 {%0,%1,%2,%3}, [%4];\n"
      : "=r"(r[0]), "=r"(r[1]), "=r"(r[2]), "=r"(r[3]) : "r"(saddr));
}
__device__ __forceinline__ void ldsm_x4_t(uint32_t r[4], uint32_t saddr){
    asm volatile("ldmatrix.sync.aligned.m8n8.x4.trans.shared.b16 {%0,%1,%2,%3}, [%4];\n"
      : "=r"(r[0]), "=r"(r[1]), "=r"(r[2]), "=r"(r[3]) : "r"(saddr));
}
__device__ __forceinline__ void cp_async16(void* sdst, const void* gsrc){
    uint32_t s = (uint32_t)__cvta_generic_to_shared(sdst);
    asm volatile("cp.async.cg.shared.global [%0], [%1], 16;\n" :: "r"(s), "l"(gsrc));
}
__device__ __forceinline__ uint32_t h2u(__half2 h){ return *(uint32_t*)&h; }

/* -------- pre-pass: fp32 -> fp16 -------- */
__global__ void __launch_bounds__(256)
cvt_h_kernel(const float* __restrict__ in, __half* __restrict__ out, int n4)
{
    int i = blockIdx.x*256 + threadIdx.x;
    if (i >= n4) return;
    float4 v = ((const float4*)in)[i];
    ((__half2*)out)[2*i  ] = __floats2half2_rn(v.x, v.y);
    ((__half2*)out)[2*i+1] = __floats2half2_rn(v.z, v.w);
}

/* -------- pre-pass: padded fp16 cmb[w][h][row 64][m 64] -------- */
__global__ void __launch_bounds__(256)
cmb_kernel(const float* __restrict__ mask, const float* __restrict__ rpb)
{
    int i = blockIdx.x*256 + threadIdx.x;
    if (i >= NWIN*NH*64*64) return;
    int w  = i / (NH*64*64);
    int r1 = i - w*(NH*64*64);
    int h  = r1 / (64*64);
    int rm = r1 - h*(64*64);
    int row = rm >> 6, m = rm & 63;
    float val;
    if (m >= NTOK)        val = -30000.f;          /* kills softmax for pad cols */
    else if (row >= NTOK) val = 0.f;               /* unused rows */
    else {
        int ri = row/7, ci = row - ri*7;
        int rj = m  /7, cj = m   - rj*7;
        int idx = ((ri - rj + 6)*13 + (ci - cj + 6))*NH + h;
        val = rpb[idx] + mask[(size_t)w*NTOK*NTOK + row*NTOK + m];
    }
    g_cmbh[i] = __float2half_rn(val);
}

/* ---------------- GEMM: C = A(Mx384) * B(Nx384)^T + bias, fp16, 3-stage ----
   MODE 0: A = g_atth, write fp32 out (proj)
   MODE 1: A = g_xh, scatter q*SCALE,k,v (all coalesced) -> g_qkv3 (fp16)     */
template<int MODE>
__global__ void __launch_bounds__(256, 2)
gemm_tn_kernel(const __half* __restrict__ Bw,
               const float* __restrict__ bias, float* __restrict__ out, int N)
{
    extern __shared__ uint32_t smem[];
    uint32_t* As = smem;                    /* [NSTG][BM][SAW] */
    uint32_t* Bs = smem + NSTG*BM*SAW;      /* [NSTG][BN][SAW] */

    const int bm = blockIdx.y, bn = blockIdx.x;
    const int tid = threadIdx.x;
    const int warp = tid >> 5, lane = tid & 31;
    const int wm = warp >> 2, wn = warp & 3;
    const int qt = lane >> 2, qr = lane & 3;
    const int K = 384;

    const __half* Ap = (MODE == 0) ? g_atth : g_xh;

    float acc[4][4][4];
    #pragma unroll
    for (int i=0;i<4;i++)
      #pragma unroll
      for (int j=0;j<4;j++)
        #pragma unroll
        for (int c=0;c<4;c++) acc[i][j][c]=0.f;

    const uint32_t s0 = (uint32_t)__cvta_generic_to_shared(smem);
    const uint32_t aAddr0 = s0
        + ((wm*64 + (lane & 15))*SAW + (lane >> 4)*4)*4;
    const uint32_t bAddr0 = s0 + NSTG*BM*SAW*4
        + ((wn*32 + (lane & 7) + ((lane >> 4) & 1)*8)*SAW + ((lane >> 3) & 1)*4)*4;
    const uint32_t ASTG = BM*SAW*4;
    const uint32_t BSTG = BN*SAW*4;

    #define LOAD_TILE(buf, ksi) do {                                              \
        int koff = (ksi)*BK;                                                      \
        _Pragma("unroll")                                                         \
        for (int i=0;i<8;i++){                                                    \
            int chunk = tid + 256*i;                                              \
            int mat = chunk >> 10; int ch = chunk & 1023;                         \
            int row = ch >> 3, c16 = ch & 7;                                      \
            const __half* g = mat                                                 \
              ? Bw + (size_t)(bn*BN + row)*K + koff + c16*8                       \
              : Ap + (size_t)(bm*BM + row)*K + koff + c16*8;                      \
            uint32_t* s = (mat ? &Bs[(buf)*BN*SAW] : &As[(buf)*BM*SAW])           \
                          + row*SAW + c16*4;                                      \
            cp_async16(s, g);                                                     \
        }                                                                         \
        asm volatile("cp.async.commit_group;\n" ::);                              \
    } while(0)

    LOAD_TILE(0, 0);
    LOAD_TILE(1, 1);

    #pragma unroll
    for (int ks = 0; ks < NKT; ks++){
        /* tile ks ready: all but the newest group retired (groups retire
           in order). Last iteration: nothing else in flight -> wait 0.    */
        if (ks < NKT-1) asm volatile("cp.async.wait_group 1;\n" ::);
        else            asm volatile("cp.async.wait_group 0;\n" ::);
        __syncthreads();   /* tile ks visible everywhere AND all warps done
                              with MMA(ks-1) -> safe to overwrite its buffer */
        if (ks + 2 < NKT) LOAD_TILE((ks+2)%NSTG, ks+2);

        const uint32_t aB = aAddr0 + (ks%NSTG)*ASTG;
        const uint32_t bB = bAddr0 + (ks%NSTG)*BSTG;

        #pragma unroll
        for (int kst = 0; kst < 4; kst++){
            uint32_t bf[2][4];
            ldsm_x4(bf[0], bB + kst*32);
            ldsm_x4(bf[1], bB + 16*SAW*4 + kst*32);
            uint32_t af[4][4];
            #pragma unroll
            for (int mt=0; mt<4; mt++)
                ldsm_x4(af[mt], aB + mt*16*SAW*4 + kst*32);
            #pragma unroll
            for (int mt=0; mt<4; mt++)
                #pragma unroll
                for (int nt=0; nt<4; nt++)
                    mma16(acc[mt][nt], af[mt][0], af[mt][1], af[mt][2], af[mt][3],
                          bf[nt>>1][(nt&1)*2], bf[nt>>1][(nt&1)*2+1]);
        }
    }
    #undef LOAD_TILE

    if (MODE == 1){
        #pragma unroll
        for (int mt=0; mt<4; mt++){
            #pragma unroll
            for (int cc=0; cc<2; cc++){
                int gm  = bm*BM + wm*64 + mt*16 + qt + cc*8;
                int bwi = gm / NTOK;
                int tok = gm - bwi*NTOK;
                #pragma unroll
                for (int nt=0; nt<4; nt++){
                    int gn0 = bn*BN + wn*32 + nt*8 + 2*qr;
                    float v0 = acc[mt][nt][cc*2    ] + bias[gn0];
                    float v1 = acc[mt][nt][cc*2 + 1] + bias[gn0+1];
                    int which = gn0 / CDIM;
                    int rest  = gn0 - which*CDIM;
                    int h = rest >> 5, d = rest & 31;
                    float sc = (which == 0) ? SCALE : 1.f;
                    __half* dst = g_qkv3
                        + ((size_t)which*B_WIN*NH + (size_t)bwi*NH + h)*(64*HD)
                        + tok*HD + d;
                    *(__half2*)dst = __floats2half2_rn(v0*sc, v1*sc);
                }
            }
        }
    } else {
        #pragma unroll
        for (int mt=0; mt<4; mt++){
            #pragma unroll
            for (int cc=0; cc<2; cc++){
                int gm = bm*BM + wm*64 + mt*16 + qt + cc*8;
                #pragma unroll
                for (int nt=0; nt<4; nt++){
                    int gn0 = bn*BN + wn*32 + nt*8 + 2*qr;
                    out[(size_t)gm*N + gn0    ] = acc[mt][nt][cc*2    ] + bias[gn0];
                    out[(size_t)gm*N + gn0 + 1] = acc[mt][nt][cc*2 + 1] + bias[gn0+1];
                }
            }
        }
    }
}

/* ---------------- attention: one CTA per (b, h) --------------------------
   All tiles via cp.async (q/k/v have zero-padded rows 49-63 in gmem).
   V stored row-major [tok][d]; transposed at load via ldmatrix.x4.trans.
   P tile aliases cmb tile (cmb fully consumed before P written).            */
__global__ void __launch_bounds__(128, 8)
attn_kernel()
{
    /* word strides: qs/ksm/vsm 20, csps 36 (conflict-free by construction) */
    __shared__ uint32_t qs[64*20], ksm[64*20], vsm[64*20], csps[64*36];

    const int b = blockIdx.y, h = blockIdx.x;
    const int tid = threadIdx.x;
    const int warp = tid >> 5, lane = tid & 31;
    const int qt = lane >> 2, qr = lane & 3;

    const size_t blk = ((size_t)b*NH + h)*(64*HD);
    const char* qgc = (const char*)(g_qkv3 + blk);
    const char* kgc = (const char*)(g_qkv3 + (size_t)B_WIN*NH*64*HD   + blk);
    const char* vgc = (const char*)(g_qkv3 + (size_t)2*B_WIN*NH*64*HD + blk);
    const char* cgc = (const char*)(g_cmbh + ((size_t)(b & (NWIN-1))*NH + h)*(64*64));

    /* q,k,v: 64 rows x 4 chunks of 16B (row = 64B data, smem stride 80B) */
    for (int i = tid; i < 256; i += 128){
        int r = i >> 2, c = i & 3;
        cp_async16(&qs [r*20 + c*4], qgc + r*64 + c*16);
        cp_async16(&ksm[r*20 + c*4], kgc + r*64 + c*16);
        cp_async16(&vsm[r*20 + c*4], vgc + r*64 + c*16);
    }
    /* cmb: 64 rows x 8 chunks (row = 128B data, smem stride 144B) */
    for (int i = tid; i < 512; i += 128){
        int r = i >> 3, c = i & 7;
        cp_async16(&csps[r*36 + c*4], cgc + r*128 + c*16);
    }
    asm volatile("cp.async.commit_group;\n" ::);
    asm volatile("cp.async.wait_group 0;\n" ::);
    __syncthreads();

    const int r0 = warp*16 + qt;
    const uint32_t s0q = (uint32_t)__cvta_generic_to_shared(qs);
    const uint32_t s0k = (uint32_t)__cvta_generic_to_shared(ksm);
    const uint32_t s0v = (uint32_t)__cvta_generic_to_shared(vsm);
    const uint32_t s0p = (uint32_t)__cvta_generic_to_shared(csps);

    const uint32_t aQ = s0q + ((warp*16 + (lane & 15))*20 + (lane >> 4)*4)*4;
    const uint32_t bK = s0k + (((lane & 7) + ((lane >> 4) & 1)*8)*20
                               + ((lane >> 3) & 1)*4)*4;
    const uint32_t aP = s0p + ((warp*16 + (lane & 15))*36 + (lane >> 4)*4)*4;
    const uint32_t bV = s0v + (((lane & 15))*20 + (lane >> 4)*4)*4;

    /* S = q @ k^T */
    float S[8][4];
    #pragma unroll
    for (int nt=0; nt<8; nt++)
        #pragma unroll
        for (int c=0; c<4; c++) S[nt][c] = 0.f;

    #pragma unroll
    for (int kst=0; kst<2; kst++){
        uint32_t af[4];
        ldsm_x4(af, aQ + kst*32);
        uint32_t bf[4][4];
        #pragma unroll
        for (int g=0; g<4; g++)
            ldsm_x4(bf[g], bK + g*16*20*4 + kst*32);
        #pragma unroll
        for (int nt=0; nt<8; nt++)
            mma16(S[nt], af[0], af[1], af[2], af[3],
                  bf[nt>>1][(nt&1)*2], bf[nt>>1][(nt&1)*2+1]);
    }

    /* + cmb (padding baked in; consumed fully before P overwrites the tile) */
    #pragma unroll
    for (int nt=0; nt<8; nt++){
        #pragma unroll
        for (int hr=0; hr<2; hr++){
            int row = r0 + hr*8;
            uint32_t cw = csps[row*36 + nt*4 + qr];
            float2 cf = __half22float2(*(__half2*)&cw);
            S[nt][hr*2    ] += cf.x;
            S[nt][hr*2 + 1] += cf.y;
        }
    }

    /* softmax over m */
    float mx[2] = {-1e30f, -1e30f};
    #pragma unroll
    for (int nt=0; nt<8; nt++)
        #pragma unroll
        for (int c=0; c<4; c++)
            mx[c>>1] = fmaxf(mx[c>>1], S[nt][c]);
    #pragma unroll
    for (int o=1; o<4; o<<=1){
        mx[0] = fmaxf(mx[0], __shfl_xor_sync(0xffffffffu, mx[0], o));
        mx[1] = fmaxf(mx[1], __shfl_xor_sync(0xffffffffu, mx[1], o));
    }
    float sm[2] = {0.f, 0.f};
    #pragma unroll
    for (int nt=0; nt<8; nt++)
        #pragma unroll
        for (int c=0; c<4; c++){
            S[nt][c] = __expf(S[nt][c] - mx[c>>1]);
            sm[c>>1] += S[nt][c];
        }
    #pragma unroll
    for (int o=1; o<4; o<<=1){
        sm[0] += __shfl_xor_sync(0xffffffffu, sm[0], o);
        sm[1] += __shfl_xor_sync(0xffffffffu, sm[1], o);
    }

    /* P -> smem fp16, overwriting this warp's cmb slab (already consumed) */
    #pragma unroll
    for (int nt=0; nt<8; nt++){
        #pragma unroll
        for (int hr=0; hr<2; hr++){
            int row = r0 + hr*8;
            csps[row*36 + nt*4 + qr] =
                h2u(__floats2half2_rn(S[nt][hr*2], S[nt][hr*2+1]));
        }
    }
    __syncwarp();

    /* O = P @ v  (V trans-loaded from [tok][d] layout) */
    float O[4][4];
    #pragma unroll
    for (int nt=0; nt<4; nt++)
        #pragma unroll
        for (int c=0; c<4; c++) O[nt][c] = 0.f;

    #pragma unroll
    for (int ksx=0; ksx<4; ksx++){
        uint32_t af[4];
        ldsm_x4(af, aP + ksx*32);
        uint32_t bf[2][4];
        ldsm_x4_t(bf[0], bV + ksx*16*20*4);        /* d 0-15  */
        ldsm_x4_t(bf[1], bV + ksx*16*20*4 + 32);   /* d 16-31 */
        #pragma unroll
        for (int nt=0; nt<4; nt++)
            mma16(O[nt], af[0], af[1], af[2], af[3],
                  bf[nt>>1][(nt&1)*2], bf[nt>>1][(nt&1)*2+1]);
    }

    const float inv0 = 1.f / sm[0], inv1 = 1.f / sm[1];
    #pragma unroll
    for (int nt=0; nt<4; nt++){
        #pragma unroll
        for (int hr=0; hr<2; hr++){
            int row = r0 + hr*8;
            if (row < NTOK){
                int d = nt*8 + 2*qr;
                float inv = hr ? inv1 : inv0;
                *(__half2*)&g_atth[((size_t)b*NTOK + row)*CDIM + h*HD + d] =
                    __floats2half2_rn(O[nt][hr*2]*inv, O[nt][hr*2+1]*inv);
            }
        }
    }
}

extern "C" void kernel_launch(void* const* d_in, const int* in_sizes, int n_in,
                              void* d_out, int out_size)
{
    const float* x      = (const float*)d_in[0];
    const float* mask   = (const float*)d_in[1];
    const float* qkv_w  = (const float*)d_in[2];
    const float* qkv_b  = (const float*)d_in[3];
    const float* proj_w = (const float*)d_in[4];
    const float* proj_b = (const float*)d_in[5];
    const float* rpb    = (const float*)d_in[6];
    float* out = (float*)d_out;

    __half *xh, *wqkv, *wproj;
    cudaGetSymbolAddress((void**)&xh,    g_xh);
    cudaGetSymbolAddress((void**)&wqkv,  g_wqkv);
    cudaGetSymbolAddress((void**)&wproj, g_wproj);

    {
        int n1 = MTOT*CDIM/4;
        cvt_h_kernel<<<(n1+255)/256, 256>>>(x, xh, n1);
        int n2 = QKN*CDIM/4;
        cvt_h_kernel<<<(n2+255)/256, 256>>>(qkv_w, wqkv, n2);
        int n3 = CDIM*CDIM/4;
        cvt_h_kernel<<<(n3+255)/256, 256>>>(proj_w, wproj, n3);
        int nc = NWIN*NH*64*64;
        cmb_kernel<<<(nc+255)/256, 256>>>(mask, rpb);
    }

    const size_t smem_bytes = (size_t)NSTG*(BM + BN)*SAW*sizeof(uint32_t); /* 110592 */
    cudaFuncSetAttribute(gemm_tn_kernel<0>,
                         cudaFuncAttributeMaxDynamicSharedMemorySize, (int)smem_bytes);
    cudaFuncSetAttribute(gemm_tn_kernel<1>,
                         cudaFuncAttributeMaxDynamicSharedMemorySize, (int)smem_bytes);

    gemm_tn_kernel<1><<<dim3(QKN/BN, MTOT/BM), 256, smem_bytes>>>(
        wqkv, qkv_b, nullptr, QKN);

    attn_kernel<<<dim3(NH, B_WIN), 128>>>();

    gemm_tn_kernel<0><<<dim3(CDIM/BN, MTOT/BM), 256, smem_bytes>>>(
        wproj, proj_b, out, CDIM);
}